// round 11
// baseline (speedup 1.0000x reference)
#include <cuda_runtime.h>
#include <cuda_bf16.h>
#include <cstdint>

// ---------------------------------------------------------------------------
// Problem constants
// ---------------------------------------------------------------------------
#define LAYERS 4
#define HDIM   512
#define NHEAD  8
#define DHQK   32
#define DHV    64
#define QKDIM  (NHEAD * DHQK)   // 256
#define VDIM   (NHEAD * DHV)    // 512
#define FDIM   1408
#define NTOK   2048              // B*P = 8*256
#define CAPV   15.0f
#define EPSV   1e-6f

typedef __nv_bfloat16  bf16;
typedef __nv_bfloat162 bf162;

// ---------------------------------------------------------------------------
// Device scratch (static: no allocation allowed)
// ---------------------------------------------------------------------------
__device__ float g_x   [NTOK * HDIM];
__device__ float g_q   [NTOK * QKDIM];
__device__ float g_k   [NTOK * QKDIM];
__device__ float g_v   [NTOK * VDIM];
__device__ float g_og  [NTOK * VDIM];
__device__ float g_if  [NTOK * 64];
__device__ float g_gate[NTOK * FDIM];
__device__ float g_up  [NTOK * FDIM];

// bf16 hi/lo split activations (GEMM A-operands, [M][K])
__device__ bf16 g_xn_h [NTOK * HDIM];
__device__ bf16 g_xn_l [NTOK * HDIM];
__device__ bf16 g_hv_h [NTOK * VDIM];
__device__ bf16 g_hv_l [NTOK * VDIM];
__device__ bf16 g_act_h[NTOK * FDIM];
__device__ bf16 g_act_l[NTOK * FDIM];

// bf16 hi/lo split weights, TRANSPOSED to [N][K] (GEMM B-operands)
__device__ bf16 w_q_h [LAYERS * QKDIM * HDIM];
__device__ bf16 w_q_l [LAYERS * QKDIM * HDIM];
__device__ bf16 w_k_h [LAYERS * QKDIM * HDIM];
__device__ bf16 w_k_l [LAYERS * QKDIM * HDIM];
__device__ bf16 w_v_h [LAYERS * VDIM * HDIM];
__device__ bf16 w_v_l [LAYERS * VDIM * HDIM];
__device__ bf16 w_og_h[LAYERS * VDIM * HDIM];
__device__ bf16 w_og_l[LAYERS * VDIM * HDIM];
__device__ bf16 w_o_h [LAYERS * HDIM * VDIM];
__device__ bf16 w_o_l [LAYERS * HDIM * VDIM];
__device__ bf16 w_g_h [LAYERS * FDIM * HDIM];
__device__ bf16 w_g_l [LAYERS * FDIM * HDIM];
__device__ bf16 w_u_h [LAYERS * FDIM * HDIM];
__device__ bf16 w_u_l [LAYERS * FDIM * HDIM];
__device__ bf16 w_d_h [LAYERS * HDIM * FDIM];
__device__ bf16 w_d_l [LAYERS * HDIM * FDIM];
__device__ bf16 w_if_h[LAYERS * 64 * HDIM];
__device__ bf16 w_if_l[LAYERS * 64 * HDIM];

// ---------------------------------------------------------------------------
// Helpers
// ---------------------------------------------------------------------------
__device__ __forceinline__ float softcapf(float x) {
    return CAPV * tanhf(x * (1.0f / CAPV));
}
__device__ __forceinline__ float logsigf(float x) {
    return (x >= 0.0f) ? -log1pf(expf(-x)) : (x - log1pf(expf(x)));
}
__device__ __forceinline__ float sigmoidf_(float x) {
    return 1.0f / (1.0f + expf(-x));
}
__device__ __forceinline__ void cpasync16(uint32_t dst, const void* src) {
    asm volatile("cp.async.cg.shared.global [%0], [%1], 16;\n"
                 :: "r"(dst), "l"(src));
}
__device__ __forceinline__ void split_bf16(float v, bf16& h, bf16& l) {
    h = __float2bfloat16_rn(v);
    l = __float2bfloat16_rn(v - __bfloat162float(h));
}
__device__ __forceinline__ void ldsm_x4(uint32_t& r0, uint32_t& r1,
                                        uint32_t& r2, uint32_t& r3,
                                        uint32_t addr) {
    asm volatile("ldmatrix.sync.aligned.m8n8.x4.shared.b16 {%0,%1,%2,%3}, [%4];"
                 : "=r"(r0), "=r"(r1), "=r"(r2), "=r"(r3) : "r"(addr));
}

#define MMA_BF16(acc, a0, a1, a2, a3, b0, b1)                                  \
    asm volatile(                                                              \
        "mma.sync.aligned.m16n8k16.row.col.f32.bf16.bf16.f32 "                 \
        "{%0,%1,%2,%3}, {%4,%5,%6,%7}, {%8,%9}, {%0,%1,%2,%3};\n"              \
        : "+f"(acc[0]), "+f"(acc[1]), "+f"(acc[2]), "+f"(acc[3])               \
        : "r"(a0), "r"(a1), "r"(a2), "r"(a3), "r"(b0), "r"(b1))

// ---------------------------------------------------------------------------
// Weight transform: fp32 W[K][N] (per layer) -> bf16 hi/lo, transposed [N][K].
// ---------------------------------------------------------------------------
__global__ __launch_bounds__(256) void split_transpose_kernel(
    const float* __restrict__ in, bf16* __restrict__ hi,
    bf16* __restrict__ lo, int K, int N)
{
    __shared__ float t[32][33];
    const int l = blockIdx.z;
    in += (size_t)l * K * N;
    hi += (size_t)l * N * K;
    lo += (size_t)l * N * K;
    const int n0 = blockIdx.x * 32, k0 = blockIdx.y * 32;
    const int tx = threadIdx.x, ty = threadIdx.y;
#pragma unroll
    for (int j = 0; j < 4; ++j)
        t[ty + 8 * j][tx] = in[(size_t)(k0 + ty + 8 * j) * N + n0 + tx];
    __syncthreads();
#pragma unroll
    for (int j = 0; j < 4; ++j) {
        float v = t[tx][ty + 8 * j];          // (k = k0+tx, n = n0+ty+8j)
        bf16 h, lv; split_bf16(v, h, lv);
        size_t o = (size_t)(n0 + ty + 8 * j) * K + k0 + tx;
        hi[o] = h; lo[o] = lv;
    }
}

// ---------------------------------------------------------------------------
// Pack [Wi | Wf | zeros] -> transposed split [64][HDIM] per layer.
// ---------------------------------------------------------------------------
__global__ void pack_wif_kernel(const float* __restrict__ Wi,
                                const float* __restrict__ Wf,
                                bf16* __restrict__ hi, bf16* __restrict__ lo)
{
    const int l = blockIdx.x >> 6;
    const int n = blockIdx.x & 63;
    for (int k = threadIdx.x; k < HDIM; k += blockDim.x) {
        float val = 0.0f;
        if (n < NHEAD)          val = Wi[((size_t)l * HDIM + k) * NHEAD + n];
        else if (n < 2 * NHEAD) val = Wf[((size_t)l * HDIM + k) * NHEAD + (n - NHEAD)];
        bf16 h, lv; split_bf16(val, h, lv);
        size_t o = ((size_t)l * 64 + n) * HDIM + k;
        hi[o] = h; lo[o] = lv;
    }
}

// ---------------------------------------------------------------------------
// Multi-segment bf16x3 GEMM with ldmatrix fragment loads.
// C_s[M,N_s] = A[M,K] @ W_s[K,N_s] (+ Res_s)
// acc += ah*bl + al*bh + ah*bh  (fp32 accumulate)
// CTA 64x64x32, 128 threads (4 warps 2x2, warp 32x32), 2-stage cp.async.
// ---------------------------------------------------------------------------
#define MAXSEG 5
struct GemmSeg {
    const bf16*  Bh;
    const bf16*  Bl;
    float*       C;
    const float* Res;   // nullptr = no residual add
    int          N;
    int          nstart;
};
struct GemmDesc {
    int nseg;
    GemmSeg seg[MAXSEG];
};

#define BM 64
#define BN 64
#define BK 32
#define BKPH 40   // 80B rows: ldmatrix phases hit all 32 banks once (20r%32 distinct)

__global__ __launch_bounds__(128) void gemm_bf16x3_kernel(
    const bf16* __restrict__ Ahi, const bf16* __restrict__ Alo,
    int M, int K, GemmDesc d)
{
    __shared__ bf16 Ah[2][BM][BKPH];
    __shared__ bf16 Al[2][BM][BKPH];
    __shared__ bf16 Bh[2][BN][BKPH];   // [n][k]
    __shared__ bf16 Bl[2][BN][BKPH];

    // --- segment lookup (uniform per CTA) ---
    const int nblk = blockIdx.x;
    int si = 0;
#pragma unroll
    for (int t = 1; t < MAXSEG; ++t)
        if (t < d.nseg && nblk >= d.seg[t].nstart) si = t;
    const bf16* __restrict__ SBh = d.seg[si].Bh;
    const bf16* __restrict__ SBl = d.seg[si].Bl;
    float*      __restrict__ C   = d.seg[si].C;
    const float* __restrict__ Res = d.seg[si].Res;
    const int N  = d.seg[si].N;
    const int n0 = (nblk - d.seg[si].nstart) * BN;
    const int m0 = blockIdx.y * BM;

    const int tid  = threadIdx.x;
    const int warp = tid >> 5;
    const int lane = tid & 31;
    const int wm   = (warp >> 1) * 32;
    const int wn   = (warp & 1) * 32;
    const int gid  = lane >> 2;          // 0..7
    const int tig  = lane & 3;           // 0..3

    // cp.async staging coords
    int rrow[2], rc16[2];
    uint32_t ah_dst[2][2], al_dst[2][2], bh_dst[2][2], bl_dst[2][2];
#pragma unroll
    for (int it = 0; it < 2; ++it) {
        int idx = tid + it * 128;
        rrow[it] = idx >> 2;
        rc16[it] = idx & 3;
#pragma unroll
        for (int s = 0; s < 2; ++s) {
            ah_dst[s][it] = (uint32_t)__cvta_generic_to_shared(&Ah[s][rrow[it]][rc16[it] * 8]);
            al_dst[s][it] = (uint32_t)__cvta_generic_to_shared(&Al[s][rrow[it]][rc16[it] * 8]);
            bh_dst[s][it] = (uint32_t)__cvta_generic_to_shared(&Bh[s][rrow[it]][rc16[it] * 8]);
            bl_dst[s][it] = (uint32_t)__cvta_generic_to_shared(&Bl[s][rrow[it]][rc16[it] * 8]);
        }
    }

    // ldmatrix per-thread base addresses (element col offset added as bytes)
    // A m16k16 x4: row = wm + mt*16 + (lane&15), col = (lane>=16)*8 (+kk)
    // B [n][k] x4 (two nt per call): row = wn + pair*16 + (lane>=16)*8 + (lane&7),
    //                                col = ((lane>>3)&1)*8 (+kk)
    const int a_row  = lane & 15;
    const int a_koff = (lane >> 4) * 8;
    const int b_row  = ((lane >> 4) & 1) * 8 + (lane & 7);
    const int b_koff = ((lane >> 3) & 1) * 8;
    uint32_t a_h_ls[2][2], a_l_ls[2][2];   // [stage][mt]
    uint32_t b_h_ls[2][2], b_l_ls[2][2];   // [stage][pair]
#pragma unroll
    for (int s = 0; s < 2; ++s) {
#pragma unroll
        for (int mt = 0; mt < 2; ++mt) {
            a_h_ls[s][mt] = (uint32_t)__cvta_generic_to_shared(
                &Ah[s][wm + mt * 16 + a_row][a_koff]);
            a_l_ls[s][mt] = (uint32_t)__cvta_generic_to_shared(
                &Al[s][wm + mt * 16 + a_row][a_koff]);
        }
#pragma unroll
        for (int p = 0; p < 2; ++p) {
            b_h_ls[s][p] = (uint32_t)__cvta_generic_to_shared(
                &Bh[s][wn + p * 16 + b_row][b_koff]);
            b_l_ls[s][p] = (uint32_t)__cvta_generic_to_shared(
                &Bl[s][wn + p * 16 + b_row][b_koff]);
        }
    }

    float acc[2][4][4];
#pragma unroll
    for (int mt = 0; mt < 2; ++mt)
#pragma unroll
        for (int nt = 0; nt < 4; ++nt)
#pragma unroll
            for (int r = 0; r < 4; ++r) acc[mt][nt][r] = 0.0f;

    const int nk = K / BK;

#pragma unroll
    for (int it = 0; it < 2; ++it) {
        cpasync16(ah_dst[0][it], Ahi + (size_t)(m0 + rrow[it]) * K + rc16[it] * 8);
        cpasync16(al_dst[0][it], Alo + (size_t)(m0 + rrow[it]) * K + rc16[it] * 8);
        cpasync16(bh_dst[0][it], SBh + (size_t)(n0 + rrow[it]) * K + rc16[it] * 8);
        cpasync16(bl_dst[0][it], SBl + (size_t)(n0 + rrow[it]) * K + rc16[it] * 8);
    }
    asm volatile("cp.async.commit_group;\n");

    for (int kt = 0; kt < nk; ++kt) {
        const int cur = kt & 1;
        if (kt + 1 < nk) {
            const int nxt = cur ^ 1;
            const int koff = (kt + 1) * BK;
#pragma unroll
            for (int it = 0; it < 2; ++it) {
                cpasync16(ah_dst[nxt][it], Ahi + (size_t)(m0 + rrow[it]) * K + koff + rc16[it] * 8);
                cpasync16(al_dst[nxt][it], Alo + (size_t)(m0 + rrow[it]) * K + koff + rc16[it] * 8);
                cpasync16(bh_dst[nxt][it], SBh + (size_t)(n0 + rrow[it]) * K + koff + rc16[it] * 8);
                cpasync16(bl_dst[nxt][it], SBl + (size_t)(n0 + rrow[it]) * K + koff + rc16[it] * 8);
            }
            asm volatile("cp.async.commit_group;\n");
            asm volatile("cp.async.wait_group 1;\n");
        } else {
            asm volatile("cp.async.wait_group 0;\n");
        }
        __syncthreads();

#pragma unroll
        for (int kk = 0; kk < BK; kk += 16) {
            const uint32_t kb = kk * 2;   // byte offset along k
            uint32_t ah[2][4], al[2][4], bh_[4][2], bl_[4][2];
#pragma unroll
            for (int mt = 0; mt < 2; ++mt) {
                ldsm_x4(ah[mt][0], ah[mt][1], ah[mt][2], ah[mt][3], a_h_ls[cur][mt] + kb);
                ldsm_x4(al[mt][0], al[mt][1], al[mt][2], al[mt][3], a_l_ls[cur][mt] + kb);
            }
            ldsm_x4(bh_[0][0], bh_[0][1], bh_[1][0], bh_[1][1], b_h_ls[cur][0] + kb);
            ldsm_x4(bh_[2][0], bh_[2][1], bh_[3][0], bh_[3][1], b_h_ls[cur][1] + kb);
            ldsm_x4(bl_[0][0], bl_[0][1], bl_[1][0], bl_[1][1], b_l_ls[cur][0] + kb);
            ldsm_x4(bl_[2][0], bl_[2][1], bl_[3][0], bl_[3][1], b_l_ls[cur][1] + kb);
#pragma unroll
            for (int mt = 0; mt < 2; ++mt)
#pragma unroll
                for (int nt = 0; nt < 4; ++nt) {
                    MMA_BF16(acc[mt][nt], ah[mt][0], ah[mt][1], ah[mt][2], ah[mt][3],
                             bl_[nt][0], bl_[nt][1]);
                    MMA_BF16(acc[mt][nt], al[mt][0], al[mt][1], al[mt][2], al[mt][3],
                             bh_[nt][0], bh_[nt][1]);
                    MMA_BF16(acc[mt][nt], ah[mt][0], ah[mt][1], ah[mt][2], ah[mt][3],
                             bh_[nt][0], bh_[nt][1]);
                }
        }
        __syncthreads();
    }

#pragma unroll
    for (int mt = 0; mt < 2; ++mt) {
#pragma unroll
        for (int nt = 0; nt < 4; ++nt) {
            int r0 = m0 + wm + mt * 16 + gid;
            int c  = n0 + wn + nt * 8 + tig * 2;
            float2 v0 = make_float2(acc[mt][nt][0], acc[mt][nt][1]);
            float2 v1 = make_float2(acc[mt][nt][2], acc[mt][nt][3]);
            if (Res != nullptr) {
                float2 r = *reinterpret_cast<const float2*>(Res + (size_t)r0 * N + c);
                v0.x += r.x; v0.y += r.y;
                r = *reinterpret_cast<const float2*>(Res + (size_t)(r0 + 8) * N + c);
                v1.x += r.x; v1.y += r.y;
            }
            *reinterpret_cast<float2*>(C + (size_t)r0 * N + c)       = v0;
            *reinterpret_cast<float2*>(C + (size_t)(r0 + 8) * N + c) = v1;
        }
    }
}

// ---------------------------------------------------------------------------
// RMSNorm (H=512, block=128). split!=0: write bf16 hi/lo; else fp32 out.
// ---------------------------------------------------------------------------
__global__ __launch_bounds__(128) void rmsnorm_kernel(
    const float* __restrict__ x, const float* __restrict__ w,
    float* __restrict__ out, bf16* __restrict__ out_hi,
    bf16* __restrict__ out_lo, int split)
{
    const int row = blockIdx.x, tid = threadIdx.x;
    float4 v = reinterpret_cast<const float4*>(x + (size_t)row * HDIM)[tid];
    float ss = v.x * v.x + v.y * v.y + v.z * v.z + v.w * v.w;
#pragma unroll
    for (int o = 16; o; o >>= 1) ss += __shfl_xor_sync(0xffffffffu, ss, o);
    __shared__ float sred[4];
    if ((tid & 31) == 0) sred[tid >> 5] = ss;
    __syncthreads();
    float tot = sred[0] + sred[1] + sred[2] + sred[3];
    float inv = rsqrtf(tot * (1.0f / (float)HDIM) + EPSV);
    float4 wv = reinterpret_cast<const float4*>(w)[tid];
    float4 o4 = make_float4(v.x * inv * wv.x, v.y * inv * wv.y,
                            v.z * inv * wv.z, v.w * inv * wv.w);
    if (split) {
        bf16 hx, lx, hy, ly, hz, lz, hw, lw;
        split_bf16(o4.x, hx, lx); split_bf16(o4.y, hy, ly);
        split_bf16(o4.z, hz, lz); split_bf16(o4.w, hw, lw);
        bf162* oh = reinterpret_cast<bf162*>(out_hi + (size_t)row * HDIM);
        bf162* ol = reinterpret_cast<bf162*>(out_lo + (size_t)row * HDIM);
        oh[tid * 2]     = __halves2bfloat162(hx, hy);
        oh[tid * 2 + 1] = __halves2bfloat162(hz, hw);
        ol[tid * 2]     = __halves2bfloat162(lx, ly);
        ol[tid * 2 + 1] = __halves2bfloat162(lz, lw);
    } else {
        reinterpret_cast<float4*>(out + (size_t)row * HDIM)[tid] = o4;
    }
}

// ---------------------------------------------------------------------------
// mLSTM step (zero state) + per-head RMSNorm + output gate.
// ---------------------------------------------------------------------------
__global__ __launch_bounds__(256) void mlstm_kernel(
    const float* __restrict__ q, const float* __restrict__ k,
    const float* __restrict__ v, const float* __restrict__ ogp,
    const float* __restrict__ ifp,
    const float* __restrict__ bi, const float* __restrict__ bf,
    const float* __restrict__ mhw,
    bf16* __restrict__ hv_hi, bf16* __restrict__ hv_lo)
{
    const int t = blockIdx.x;
    const int h = threadIdx.x >> 5;
    const int lane = threadIdx.x & 31;

    float ip = softcapf(ifp[(size_t)t * 64 + h]      + bi[h]);
    float fp = softcapf(ifp[(size_t)t * 64 + 8 + h]  + bf[h]);
    float flog = logsigf(fp);
    float m = fmaxf(flog, ip);
    float iact = expf(ip - m);

    float qd = q[(size_t)t * QKDIM + h * DHQK + lane];
    float kd = k[(size_t)t * QKDIM + h * DHQK + lane];
    float s = qd * kd;
#pragma unroll
    for (int o = 16; o; o >>= 1) s += __shfl_xor_sync(0xffffffffu, s, o);
    s *= 0.17677669529663687f;  // 32^-0.5

    float qn = iact * s;
    float denom = fmaxf(fabsf(qn), expf(-m)) + EPSV;
    float c = iact * s / denom;

    const int base = t * VDIM + h * DHV;
    float v0 = v[base + lane], v1 = v[base + 32 + lane];
    float h0 = c * v0, h1 = c * v1;

    float ms = h0 * h0 + h1 * h1;
#pragma unroll
    for (int o = 16; o; o >>= 1) ms += __shfl_xor_sync(0xffffffffu, ms, o);
    float inv = rsqrtf(ms * (1.0f / (float)DHV) + EPSV);

    float w0 = mhw[h * DHV + lane],      w1 = mhw[h * DHV + 32 + lane];
    float g0 = sigmoidf_(ogp[base + lane]);
    float g1 = sigmoidf_(ogp[base + 32 + lane]);
    float r0 = h0 * inv * w0 * g0;
    float r1 = h1 * inv * w1 * g1;
    bf16 rh, rl;
    split_bf16(r0, rh, rl);
    hv_hi[base + lane] = rh;           hv_lo[base + lane] = rl;
    split_bf16(r1, rh, rl);
    hv_hi[base + 32 + lane] = rh;      hv_lo[base + 32 + lane] = rl;
}

// ---------------------------------------------------------------------------
// SwiGLU: act = silu(g) * up, written split bf16
// ---------------------------------------------------------------------------
__global__ __launch_bounds__(256) void silu_mul_kernel(
    const float* __restrict__ g, const float* __restrict__ up,
    bf16* __restrict__ act_hi, bf16* __restrict__ act_lo, int n4)
{
    int i = blockIdx.x * blockDim.x + threadIdx.x;
    if (i >= n4) return;
    float4 gv = reinterpret_cast<const float4*>(g)[i];
    float4 uv = reinterpret_cast<const float4*>(up)[i];
    float4 a;
    a.x = gv.x * sigmoidf_(gv.x) * uv.x;
    a.y = gv.y * sigmoidf_(gv.y) * uv.y;
    a.z = gv.z * sigmoidf_(gv.z) * uv.z;
    a.w = gv.w * sigmoidf_(gv.w) * uv.w;
    bf16 hx, lx, hy, ly, hz, lz, hw, lw;
    split_bf16(a.x, hx, lx); split_bf16(a.y, hy, ly);
    split_bf16(a.z, hz, lz); split_bf16(a.w, hw, lw);
    bf162* oh = reinterpret_cast<bf162*>(act_hi);
    bf162* ol = reinterpret_cast<bf162*>(act_lo);
    oh[i * 2]     = __halves2bfloat162(hx, hy);
    oh[i * 2 + 1] = __halves2bfloat162(hz, hw);
    ol[i * 2]     = __halves2bfloat162(lx, ly);
    ol[i * 2 + 1] = __halves2bfloat162(lz, lw);
}

// ---------------------------------------------------------------------------
// Host launcher
// ---------------------------------------------------------------------------
static inline void* sym_addr_v(const void* sym) {
    void* p = nullptr;
    cudaGetSymbolAddress(&p, sym);
    return p;
}
#define SYMF(s)  ((float*)sym_addr_v(s))
#define SYMB(s)  ((bf16*)sym_addr_v(s))

static inline void gemm_multi(const bf16* Ahi, const bf16* Alo,
                              int M, int K, const GemmDesc& d) {
    int nb = d.seg[d.nseg - 1].nstart + d.seg[d.nseg - 1].N / BN;
    dim3 grid(nb, M / BM);
    gemm_bf16x3_kernel<<<grid, 128>>>(Ahi, Alo, M, K, d);
}

static inline void split_tr(const float* in, bf16* hi, bf16* lo, int K, int N) {
    dim3 grid(N / 32, K / 32, LAYERS);
    split_transpose_kernel<<<grid, dim3(32, 8)>>>(in, hi, lo, K, N);
}

extern "C" void kernel_launch(void* const* d_in, const int* in_sizes, int n_in,
                              void* d_out, int out_size)
{
    (void)in_sizes; (void)n_in; (void)out_size;
    const float* u       = (const float*)d_in[0];
    const float* norm1_w = (const float*)d_in[1];
    const float* Wq      = (const float*)d_in[2];
    const float* Wk      = (const float*)d_in[3];
    const float* Wv      = (const float*)d_in[4];
    const float* Wi      = (const float*)d_in[5];
    const float* bi      = (const float*)d_in[6];
    const float* Wf      = (const float*)d_in[7];
    const float* bf_     = (const float*)d_in[8];
    const float* mh_w    = (const float*)d_in[9];
    const float* Wog     = (const float*)d_in[10];
    const float* Wout    = (const float*)d_in[11];
    const float* norm2_w = (const float*)d_in[12];
    const float* W_up    = (const float*)d_in[13];
    const float* W_gate  = (const float*)d_in[14];
    const float* W_down  = (const float*)d_in[15];
    const float* final_w = (const float*)d_in[16];
    float* out = (float*)d_out;

    float* x   = SYMF(g_x);
    float* qb  = SYMF(g_q);
    float* kb  = SYMF(g_k);
    float* vb  = SYMF(g_v);
    float* ogb = SYMF(g_og);
    float* ifb = SYMF(g_if);
    float* gb  = SYMF(g_gate);
    float* ub  = SYMF(g_up);
    bf16* xnh  = SYMB(g_xn_h),  *xnl  = SYMB(g_xn_l);
    bf16* hvh  = SYMB(g_hv_h),  *hvl  = SYMB(g_hv_l);
    bf16* acth = SYMB(g_act_h), *actl = SYMB(g_act_l);

    bf16* wqh = SYMB(w_q_h),  *wql = SYMB(w_q_l);
    bf16* wkh = SYMB(w_k_h),  *wkl = SYMB(w_k_l);
    bf16* wvh = SYMB(w_v_h),  *wvl = SYMB(w_v_l);
    bf16* wogh= SYMB(w_og_h), *wogl= SYMB(w_og_l);
    bf16* woh = SYMB(w_o_h),  *wol = SYMB(w_o_l);
    bf16* wgh = SYMB(w_g_h),  *wgl = SYMB(w_g_l);
    bf16* wuh = SYMB(w_u_h),  *wul = SYMB(w_u_l);
    bf16* wdh = SYMB(w_d_h),  *wdl = SYMB(w_d_l);
    bf16* wifh= SYMB(w_if_h), *wifl= SYMB(w_if_l);

    cudaMemcpyAsync(x, u, (size_t)NTOK * HDIM * sizeof(float),
                    cudaMemcpyDeviceToDevice, 0);

    // weight transforms: fp32 [K][N] -> bf16 hi/lo [N][K], once per call
    split_tr(Wq,     wqh,  wql,  HDIM, QKDIM);
    split_tr(Wk,     wkh,  wkl,  HDIM, QKDIM);
    split_tr(Wv,     wvh,  wvl,  HDIM, VDIM);
    split_tr(Wog,    wogh, wogl, HDIM, VDIM);
    split_tr(Wout,   woh,  wol,  VDIM, HDIM);
    split_tr(W_gate, wgh,  wgl,  HDIM, FDIM);
    split_tr(W_up,   wuh,  wul,  HDIM, FDIM);
    split_tr(W_down, wdh,  wdl,  FDIM, HDIM);
    pack_wif_kernel<<<LAYERS * 64, 128>>>(Wi, Wf, wifh, wifl);

    for (int l = 0; l < LAYERS; ++l) {
        const size_t oqk = (size_t)l * QKDIM * HDIM;
        const size_t ov  = (size_t)l * VDIM * HDIM;
        const size_t of  = (size_t)l * FDIM * HDIM;
        const size_t oif = (size_t)l * 64 * HDIM;

        // --- mLSTM block ---
        rmsnorm_kernel<<<NTOK, 128>>>(x, norm1_w + l * HDIM,
                                      nullptr, xnh, xnl, 1);

        GemmDesc d1;            // q | k | v | og | if
        d1.nseg = 5;
        d1.seg[0] = { wqh + oqk,  wql + oqk,  qb,  nullptr, QKDIM, 0  };
        d1.seg[1] = { wkh + oqk,  wkl + oqk,  kb,  nullptr, QKDIM, 4  };
        d1.seg[2] = { wvh + ov,   wvl + ov,   vb,  nullptr, VDIM,  8  };
        d1.seg[3] = { wogh + ov,  wogl + ov,  ogb, nullptr, VDIM,  16 };
        d1.seg[4] = { wifh + oif, wifl + oif, ifb, nullptr, 64,    24 };
        gemm_multi(xnh, xnl, NTOK, HDIM, d1);

        mlstm_kernel<<<NTOK, 256>>>(qb, kb, vb, ogb, ifb,
                                    bi + l * NHEAD, bf_ + l * NHEAD,
                                    mh_w + (size_t)l * NHEAD * DHV, hvh, hvl);

        GemmDesc d2;            // x += hv @ Wout
        d2.nseg = 1;
        d2.seg[0] = { woh + ov, wol + ov, x, x, HDIM, 0 };
        gemm_multi(hvh, hvl, NTOK, VDIM, d2);

        // --- FFN block ---
        rmsnorm_kernel<<<NTOK, 128>>>(x, norm2_w + l * HDIM,
                                      nullptr, xnh, xnl, 1);

        GemmDesc d3;            // gate | up
        d3.nseg = 2;
        d3.seg[0] = { wgh + of, wgl + of, gb, nullptr, FDIM, 0  };
        d3.seg[1] = { wuh + of, wul + of, ub, nullptr, FDIM, 22 };
        gemm_multi(xnh, xnl, NTOK, HDIM, d3);

        silu_mul_kernel<<<(NTOK * FDIM / 4 + 255) / 256, 256>>>(
            gb, ub, acth, actl, NTOK * FDIM / 4);

        GemmDesc d4;            // x += act @ W_down
        d4.nseg = 1;
        d4.seg[0] = { wdh + (size_t)l * HDIM * FDIM,
                      wdl + (size_t)l * HDIM * FDIM, x, x, HDIM, 0 };
        gemm_multi(acth, actl, NTOK, FDIM, d4);
    }

    rmsnorm_kernel<<<NTOK, 128>>>(x, final_w, out, nullptr, nullptr, 0);
}

// round 12
// speedup vs baseline: 1.0959x; 1.0959x over previous
#include <cuda_runtime.h>
#include <cuda_bf16.h>
#include <cstdint>

// ---------------------------------------------------------------------------
// Problem constants
// ---------------------------------------------------------------------------
#define LAYERS 4
#define HDIM   512
#define NHEAD  8
#define DHQK   32
#define DHV    64
#define QKDIM  (NHEAD * DHQK)   // 256
#define VDIM   (NHEAD * DHV)    // 512
#define FDIM   1408
#define NTOK   2048              // B*P = 8*256
#define CAPV   15.0f
#define EPSV   1e-6f

typedef __nv_bfloat16  bf16;
typedef __nv_bfloat162 bf162;

// ---------------------------------------------------------------------------
// Device scratch (static: no allocation allowed)
// ---------------------------------------------------------------------------
__device__ float g_x   [NTOK * HDIM];
__device__ float g_q   [NTOK * QKDIM];
__device__ float g_k   [NTOK * QKDIM];
__device__ float g_v   [NTOK * VDIM];
__device__ float g_og  [NTOK * VDIM];
__device__ float g_if  [NTOK * 64];
__device__ float g_gate[NTOK * FDIM];
__device__ float g_up  [NTOK * FDIM];

// bf16 hi/lo split activations (GEMM A-operands, [M][K])
__device__ bf16 g_xn_h [NTOK * HDIM];
__device__ bf16 g_xn_l [NTOK * HDIM];
__device__ bf16 g_hv_h [NTOK * VDIM];
__device__ bf16 g_hv_l [NTOK * VDIM];
__device__ bf16 g_act_h[NTOK * FDIM];
__device__ bf16 g_act_l[NTOK * FDIM];

// bf16 hi/lo split weights, TRANSPOSED to [N][K] (GEMM B-operands)
__device__ bf16 w_q_h [LAYERS * QKDIM * HDIM];
__device__ bf16 w_q_l [LAYERS * QKDIM * HDIM];
__device__ bf16 w_k_h [LAYERS * QKDIM * HDIM];
__device__ bf16 w_k_l [LAYERS * QKDIM * HDIM];
__device__ bf16 w_v_h [LAYERS * VDIM * HDIM];
__device__ bf16 w_v_l [LAYERS * VDIM * HDIM];
__device__ bf16 w_og_h[LAYERS * VDIM * HDIM];
__device__ bf16 w_og_l[LAYERS * VDIM * HDIM];
__device__ bf16 w_o_h [LAYERS * HDIM * VDIM];
__device__ bf16 w_o_l [LAYERS * HDIM * VDIM];
__device__ bf16 w_g_h [LAYERS * FDIM * HDIM];
__device__ bf16 w_g_l [LAYERS * FDIM * HDIM];
__device__ bf16 w_u_h [LAYERS * FDIM * HDIM];
__device__ bf16 w_u_l [LAYERS * FDIM * HDIM];
__device__ bf16 w_d_h [LAYERS * HDIM * FDIM];
__device__ bf16 w_d_l [LAYERS * HDIM * FDIM];
__device__ bf16 w_if_h[LAYERS * 64 * HDIM];
__device__ bf16 w_if_l[LAYERS * 64 * HDIM];

// ---------------------------------------------------------------------------
// Helpers
// ---------------------------------------------------------------------------
__device__ __forceinline__ float softcapf(float x) {
    return CAPV * tanhf(x * (1.0f / CAPV));
}
__device__ __forceinline__ float logsigf(float x) {
    return (x >= 0.0f) ? -log1pf(expf(-x)) : (x - log1pf(expf(x)));
}
__device__ __forceinline__ float sigmoidf_(float x) {
    return 1.0f / (1.0f + expf(-x));
}
__device__ __forceinline__ void cpasync16(uint32_t dst, const void* src) {
    asm volatile("cp.async.cg.shared.global [%0], [%1], 16;\n"
                 :: "r"(dst), "l"(src));
}
__device__ __forceinline__ void split_bf16(float v, bf16& h, bf16& l) {
    h = __float2bfloat16_rn(v);
    l = __float2bfloat16_rn(v - __bfloat162float(h));
}

#define MMA_BF16(acc, a0, a1, a2, a3, b0, b1)                                  \
    asm volatile(                                                              \
        "mma.sync.aligned.m16n8k16.row.col.f32.bf16.bf16.f32 "                 \
        "{%0,%1,%2,%3}, {%4,%5,%6,%7}, {%8,%9}, {%0,%1,%2,%3};\n"              \
        : "+f"(acc[0]), "+f"(acc[1]), "+f"(acc[2]), "+f"(acc[3])               \
        : "r"(a0), "r"(a1), "r"(a2), "r"(a3), "r"(b0), "r"(b1))

// ---------------------------------------------------------------------------
// Plain device copy (replaces cudaMemcpyAsync for deterministic launch order)
// ---------------------------------------------------------------------------
__global__ __launch_bounds__(256) void copy_kernel(
    const float* __restrict__ in, float* __restrict__ out, int n4)
{
    int i = blockIdx.x * blockDim.x + threadIdx.x;
    if (i < n4) reinterpret_cast<float4*>(out)[i] =
        reinterpret_cast<const float4*>(in)[i];
}

// ---------------------------------------------------------------------------
// Multi-segment weight transform: fp32 W[K][N] -> bf16 hi/lo transposed [N][K].
// One launch handles several weight tensors (segments). grid.x enumerates
// 32x32 tiles across segments, grid.z = layer.
// ---------------------------------------------------------------------------
#define MAXWSEG 5
struct SplitSeg {
    const float* in;   // [LAYERS][K][N]
    bf16* hi;          // [LAYERS][N][K]
    bf16* lo;
    int K, N;
    int tstart;        // first global tile index of this segment
};
struct SplitDesc {
    int nseg;
    SplitSeg seg[MAXWSEG];
};

__global__ __launch_bounds__(256) void split_transpose_multi_kernel(SplitDesc d)
{
    __shared__ float t[32][33];
    const int tile = blockIdx.x;
    int si = 0;
#pragma unroll
    for (int s = 1; s < MAXWSEG; ++s)
        if (s < d.nseg && tile >= d.seg[s].tstart) si = s;
    const SplitSeg& sg = d.seg[si];
    const int l = blockIdx.z;
    const float* in = sg.in + (size_t)l * sg.K * sg.N;
    bf16* hi = sg.hi + (size_t)l * sg.N * sg.K;
    bf16* lo = sg.lo + (size_t)l * sg.N * sg.K;

    const int tl   = tile - sg.tstart;
    const int ntn  = sg.N / 32;
    const int n0   = (tl % ntn) * 32;
    const int k0   = (tl / ntn) * 32;
    const int tx = threadIdx.x, ty = threadIdx.y;
#pragma unroll
    for (int j = 0; j < 4; ++j)
        t[ty + 8 * j][tx] = in[(size_t)(k0 + ty + 8 * j) * sg.N + n0 + tx];
    __syncthreads();
#pragma unroll
    for (int j = 0; j < 4; ++j) {
        float v = t[tx][ty + 8 * j];          // (k = k0+tx, n = n0+ty+8j)
        bf16 h, lv; split_bf16(v, h, lv);
        size_t o = (size_t)(n0 + ty + 8 * j) * sg.K + k0 + tx;
        hi[o] = h; lo[o] = lv;
    }
}

// ---------------------------------------------------------------------------
// Pack [Wi | Wf | zeros] -> transposed split [64][HDIM] per layer.
// ---------------------------------------------------------------------------
__global__ void pack_wif_kernel(const float* __restrict__ Wi,
                                const float* __restrict__ Wf,
                                bf16* __restrict__ hi, bf16* __restrict__ lo)
{
    const int l = blockIdx.x >> 6;
    const int n = blockIdx.x & 63;
    for (int k = threadIdx.x; k < HDIM; k += blockDim.x) {
        float val = 0.0f;
        if (n < NHEAD)          val = Wi[((size_t)l * HDIM + k) * NHEAD + n];
        else if (n < 2 * NHEAD) val = Wf[((size_t)l * HDIM + k) * NHEAD + (n - NHEAD)];
        bf16 h, lv; split_bf16(val, h, lv);
        size_t o = ((size_t)l * 64 + n) * HDIM + k;
        hi[o] = h; lo[o] = lv;
    }
}

// ---------------------------------------------------------------------------
// Multi-segment bf16x3 GEMM (R10-proven inner loop: scalar LDS fragment loads).
// C_s[M,N_s] = A[M,K] @ W_s[K,N_s] (+ Res_s)
// acc += ah*bl + al*bh + ah*bh  (fp32 accumulate)
// CTA 64x64x32, 128 threads (4 warps 2x2, warp 32x32), 2-stage cp.async.
// ---------------------------------------------------------------------------
#define MAXSEG 5
struct GemmSeg {
    const bf16*  Bh;
    const bf16*  Bl;
    float*       C;
    const float* Res;   // nullptr = no residual add
    int          N;
    int          nstart;
};
struct GemmDesc {
    int nseg;
    GemmSeg seg[MAXSEG];
};

#define BM 64
#define BN 64
#define BK 32
#define BKPH 40   // 80B rows: banks (20r)%32 distinct -> conflict-free

__global__ __launch_bounds__(128) void gemm_bf16x3_kernel(
    const bf16* __restrict__ Ahi, const bf16* __restrict__ Alo,
    int M, int K, GemmDesc d)
{
    __shared__ bf16 Ah[2][BM][BKPH];
    __shared__ bf16 Al[2][BM][BKPH];
    __shared__ bf16 Bh[2][BN][BKPH];   // [n][k]
    __shared__ bf16 Bl[2][BN][BKPH];

    // --- segment lookup (uniform per CTA) ---
    const int nblk = blockIdx.x;
    int si = 0;
#pragma unroll
    for (int t = 1; t < MAXSEG; ++t)
        if (t < d.nseg && nblk >= d.seg[t].nstart) si = t;
    const bf16* __restrict__ SBh = d.seg[si].Bh;
    const bf16* __restrict__ SBl = d.seg[si].Bl;
    float*      __restrict__ C   = d.seg[si].C;
    const float* __restrict__ Res = d.seg[si].Res;
    const int N  = d.seg[si].N;
    const int n0 = (nblk - d.seg[si].nstart) * BN;
    const int m0 = blockIdx.y * BM;

    const int tid  = threadIdx.x;
    const int warp = tid >> 5;
    const int lane = tid & 31;
    const int wm   = (warp >> 1) * 32;
    const int wn   = (warp & 1) * 32;
    const int gid  = lane >> 2;          // 0..7
    const int tig  = lane & 3;           // 0..3

    int rrow[2], rc16[2];
    uint32_t ah_dst[2][2], al_dst[2][2], bh_dst[2][2], bl_dst[2][2];
#pragma unroll
    for (int it = 0; it < 2; ++it) {
        int idx = tid + it * 128;
        rrow[it] = idx >> 2;
        rc16[it] = idx & 3;
#pragma unroll
        for (int s = 0; s < 2; ++s) {
            ah_dst[s][it] = (uint32_t)__cvta_generic_to_shared(&Ah[s][rrow[it]][rc16[it] * 8]);
            al_dst[s][it] = (uint32_t)__cvta_generic_to_shared(&Al[s][rrow[it]][rc16[it] * 8]);
            bh_dst[s][it] = (uint32_t)__cvta_generic_to_shared(&Bh[s][rrow[it]][rc16[it] * 8]);
            bl_dst[s][it] = (uint32_t)__cvta_generic_to_shared(&Bl[s][rrow[it]][rc16[it] * 8]);
        }
    }

    float acc[2][4][4];
#pragma unroll
    for (int mt = 0; mt < 2; ++mt)
#pragma unroll
        for (int nt = 0; nt < 4; ++nt)
#pragma unroll
            for (int r = 0; r < 4; ++r) acc[mt][nt][r] = 0.0f;

    const int nk = K / BK;

#pragma unroll
    for (int it = 0; it < 2; ++it) {
        cpasync16(ah_dst[0][it], Ahi + (size_t)(m0 + rrow[it]) * K + rc16[it] * 8);
        cpasync16(al_dst[0][it], Alo + (size_t)(m0 + rrow[it]) * K + rc16[it] * 8);
        cpasync16(bh_dst[0][it], SBh + (size_t)(n0 + rrow[it]) * K + rc16[it] * 8);
        cpasync16(bl_dst[0][it], SBl + (size_t)(n0 + rrow[it]) * K + rc16[it] * 8);
    }
    asm volatile("cp.async.commit_group;\n");

    for (int kt = 0; kt < nk; ++kt) {
        const int cur = kt & 1;
        if (kt + 1 < nk) {
            const int nxt = cur ^ 1;
            const int koff = (kt + 1) * BK;
#pragma unroll
            for (int it = 0; it < 2; ++it) {
                cpasync16(ah_dst[nxt][it], Ahi + (size_t)(m0 + rrow[it]) * K + koff + rc16[it] * 8);
                cpasync16(al_dst[nxt][it], Alo + (size_t)(m0 + rrow[it]) * K + koff + rc16[it] * 8);
                cpasync16(bh_dst[nxt][it], SBh + (size_t)(n0 + rrow[it]) * K + koff + rc16[it] * 8);
                cpasync16(bl_dst[nxt][it], SBl + (size_t)(n0 + rrow[it]) * K + koff + rc16[it] * 8);
            }
            asm volatile("cp.async.commit_group;\n");
            asm volatile("cp.async.wait_group 1;\n");
        } else {
            asm volatile("cp.async.wait_group 0;\n");
        }
        __syncthreads();

#pragma unroll
        for (int kk = 0; kk < BK; kk += 16) {
            uint32_t ah[2][4], al[2][4], bh_[4][2], bl_[4][2];
#pragma unroll
            for (int mt = 0; mt < 2; ++mt) {
                int r = wm + mt * 16 + gid;
                ah[mt][0] = *(const uint32_t*)&Ah[cur][r    ][kk + 2 * tig];
                ah[mt][1] = *(const uint32_t*)&Ah[cur][r + 8][kk + 2 * tig];
                ah[mt][2] = *(const uint32_t*)&Ah[cur][r    ][kk + 2 * tig + 8];
                ah[mt][3] = *(const uint32_t*)&Ah[cur][r + 8][kk + 2 * tig + 8];
                al[mt][0] = *(const uint32_t*)&Al[cur][r    ][kk + 2 * tig];
                al[mt][1] = *(const uint32_t*)&Al[cur][r + 8][kk + 2 * tig];
                al[mt][2] = *(const uint32_t*)&Al[cur][r    ][kk + 2 * tig + 8];
                al[mt][3] = *(const uint32_t*)&Al[cur][r + 8][kk + 2 * tig + 8];
            }
#pragma unroll
            for (int nt = 0; nt < 4; ++nt) {
                int c = wn + nt * 8 + gid;
                bh_[nt][0] = *(const uint32_t*)&Bh[cur][c][kk + 2 * tig];
                bh_[nt][1] = *(const uint32_t*)&Bh[cur][c][kk + 2 * tig + 8];
                bl_[nt][0] = *(const uint32_t*)&Bl[cur][c][kk + 2 * tig];
                bl_[nt][1] = *(const uint32_t*)&Bl[cur][c][kk + 2 * tig + 8];
            }
#pragma unroll
            for (int mt = 0; mt < 2; ++mt)
#pragma unroll
                for (int nt = 0; nt < 4; ++nt) {
                    MMA_BF16(acc[mt][nt], ah[mt][0], ah[mt][1], ah[mt][2], ah[mt][3],
                             bl_[nt][0], bl_[nt][1]);
                    MMA_BF16(acc[mt][nt], al[mt][0], al[mt][1], al[mt][2], al[mt][3],
                             bh_[nt][0], bh_[nt][1]);
                    MMA_BF16(acc[mt][nt], ah[mt][0], ah[mt][1], ah[mt][2], ah[mt][3],
                             bh_[nt][0], bh_[nt][1]);
                }
        }
        __syncthreads();
    }

#pragma unroll
    for (int mt = 0; mt < 2; ++mt) {
#pragma unroll
        for (int nt = 0; nt < 4; ++nt) {
            int r0 = m0 + wm + mt * 16 + gid;
            int c  = n0 + wn + nt * 8 + tig * 2;
            float2 v0 = make_float2(acc[mt][nt][0], acc[mt][nt][1]);
            float2 v1 = make_float2(acc[mt][nt][2], acc[mt][nt][3]);
            if (Res != nullptr) {
                float2 r = *reinterpret_cast<const float2*>(Res + (size_t)r0 * N + c);
                v0.x += r.x; v0.y += r.y;
                r = *reinterpret_cast<const float2*>(Res + (size_t)(r0 + 8) * N + c);
                v1.x += r.x; v1.y += r.y;
            }
            *reinterpret_cast<float2*>(C + (size_t)r0 * N + c)       = v0;
            *reinterpret_cast<float2*>(C + (size_t)(r0 + 8) * N + c) = v1;
        }
    }
}

// ---------------------------------------------------------------------------
// RMSNorm (H=512, block=128). split!=0: write bf16 hi/lo; else fp32 out.
// ---------------------------------------------------------------------------
__global__ __launch_bounds__(128) void rmsnorm_kernel(
    const float* __restrict__ x, const float* __restrict__ w,
    float* __restrict__ out, bf16* __restrict__ out_hi,
    bf16* __restrict__ out_lo, int split)
{
    const int row = blockIdx.x, tid = threadIdx.x;
    float4 v = reinterpret_cast<const float4*>(x + (size_t)row * HDIM)[tid];
    float ss = v.x * v.x + v.y * v.y + v.z * v.z + v.w * v.w;
#pragma unroll
    for (int o = 16; o; o >>= 1) ss += __shfl_xor_sync(0xffffffffu, ss, o);
    __shared__ float sred[4];
    if ((tid & 31) == 0) sred[tid >> 5] = ss;
    __syncthreads();
    float tot = sred[0] + sred[1] + sred[2] + sred[3];
    float inv = rsqrtf(tot * (1.0f / (float)HDIM) + EPSV);
    float4 wv = reinterpret_cast<const float4*>(w)[tid];
    float4 o4 = make_float4(v.x * inv * wv.x, v.y * inv * wv.y,
                            v.z * inv * wv.z, v.w * inv * wv.w);
    if (split) {
        bf16 hx, lx, hy, ly, hz, lz, hw, lw;
        split_bf16(o4.x, hx, lx); split_bf16(o4.y, hy, ly);
        split_bf16(o4.z, hz, lz); split_bf16(o4.w, hw, lw);
        bf162* oh = reinterpret_cast<bf162*>(out_hi + (size_t)row * HDIM);
        bf162* ol = reinterpret_cast<bf162*>(out_lo + (size_t)row * HDIM);
        oh[tid * 2]     = __halves2bfloat162(hx, hy);
        oh[tid * 2 + 1] = __halves2bfloat162(hz, hw);
        ol[tid * 2]     = __halves2bfloat162(lx, ly);
        ol[tid * 2 + 1] = __halves2bfloat162(lz, lw);
    } else {
        reinterpret_cast<float4*>(out + (size_t)row * HDIM)[tid] = o4;
    }
}

// ---------------------------------------------------------------------------
// mLSTM step (zero state) + per-head RMSNorm + output gate.
// ---------------------------------------------------------------------------
__global__ __launch_bounds__(256) void mlstm_kernel(
    const float* __restrict__ q, const float* __restrict__ k,
    const float* __restrict__ v, const float* __restrict__ ogp,
    const float* __restrict__ ifp,
    const float* __restrict__ bi, const float* __restrict__ bf,
    const float* __restrict__ mhw,
    bf16* __restrict__ hv_hi, bf16* __restrict__ hv_lo)
{
    const int t = blockIdx.x;
    const int h = threadIdx.x >> 5;
    const int lane = threadIdx.x & 31;

    float ip = softcapf(ifp[(size_t)t * 64 + h]      + bi[h]);
    float fp = softcapf(ifp[(size_t)t * 64 + 8 + h]  + bf[h]);
    float flog = logsigf(fp);
    float m = fmaxf(flog, ip);
    float iact = expf(ip - m);

    float qd = q[(size_t)t * QKDIM + h * DHQK + lane];
    float kd = k[(size_t)t * QKDIM + h * DHQK + lane];
    float s = qd * kd;
#pragma unroll
    for (int o = 16; o; o >>= 1) s += __shfl_xor_sync(0xffffffffu, s, o);
    s *= 0.17677669529663687f;  // 32^-0.5

    float qn = iact * s;
    float denom = fmaxf(fabsf(qn), expf(-m)) + EPSV;
    float c = iact * s / denom;

    const int base = t * VDIM + h * DHV;
    float v0 = v[base + lane], v1 = v[base + 32 + lane];
    float h0 = c * v0, h1 = c * v1;

    float ms = h0 * h0 + h1 * h1;
#pragma unroll
    for (int o = 16; o; o >>= 1) ms += __shfl_xor_sync(0xffffffffu, ms, o);
    float inv = rsqrtf(ms * (1.0f / (float)DHV) + EPSV);

    float w0 = mhw[h * DHV + lane],      w1 = mhw[h * DHV + 32 + lane];
    float g0 = sigmoidf_(ogp[base + lane]);
    float g1 = sigmoidf_(ogp[base + 32 + lane]);
    float r0 = h0 * inv * w0 * g0;
    float r1 = h1 * inv * w1 * g1;
    bf16 rh, rl;
    split_bf16(r0, rh, rl);
    hv_hi[base + lane] = rh;           hv_lo[base + lane] = rl;
    split_bf16(r1, rh, rl);
    hv_hi[base + 32 + lane] = rh;      hv_lo[base + 32 + lane] = rl;
}

// ---------------------------------------------------------------------------
// SwiGLU: act = silu(g) * up, written split bf16
// ---------------------------------------------------------------------------
__global__ __launch_bounds__(256) void silu_mul_kernel(
    const float* __restrict__ g, const float* __restrict__ up,
    bf16* __restrict__ act_hi, bf16* __restrict__ act_lo, int n4)
{
    int i = blockIdx.x * blockDim.x + threadIdx.x;
    if (i >= n4) return;
    float4 gv = reinterpret_cast<const float4*>(g)[i];
    float4 uv = reinterpret_cast<const float4*>(up)[i];
    float4 a;
    a.x = gv.x * sigmoidf_(gv.x) * uv.x;
    a.y = gv.y * sigmoidf_(gv.y) * uv.y;
    a.z = gv.z * sigmoidf_(gv.z) * uv.z;
    a.w = gv.w * sigmoidf_(gv.w) * uv.w;
    bf16 hx, lx, hy, ly, hz, lz, hw, lw;
    split_bf16(a.x, hx, lx); split_bf16(a.y, hy, ly);
    split_bf16(a.z, hz, lz); split_bf16(a.w, hw, lw);
    bf162* oh = reinterpret_cast<bf162*>(act_hi);
    bf162* ol = reinterpret_cast<bf162*>(act_lo);
    oh[i * 2]     = __halves2bfloat162(hx, hy);
    oh[i * 2 + 1] = __halves2bfloat162(hz, hw);
    ol[i * 2]     = __halves2bfloat162(lx, ly);
    ol[i * 2 + 1] = __halves2bfloat162(lz, lw);
}

// ---------------------------------------------------------------------------
// Host launcher
// ---------------------------------------------------------------------------
static inline void* sym_addr_v(const void* sym) {
    void* p = nullptr;
    cudaGetSymbolAddress(&p, sym);
    return p;
}
#define SYMF(s)  ((float*)sym_addr_v(s))
#define SYMB(s)  ((bf16*)sym_addr_v(s))

static inline void gemm_multi(const bf16* Ahi, const bf16* Alo,
                              int M, int K, const GemmDesc& d) {
    int nb = d.seg[d.nseg - 1].nstart + d.seg[d.nseg - 1].N / BN;
    dim3 grid(nb, M / BM);
    gemm_bf16x3_kernel<<<grid, 128>>>(Ahi, Alo, M, K, d);
}

extern "C" void kernel_launch(void* const* d_in, const int* in_sizes, int n_in,
                              void* d_out, int out_size)
{
    (void)in_sizes; (void)n_in; (void)out_size;
    const float* u       = (const float*)d_in[0];
    const float* norm1_w = (const float*)d_in[1];
    const float* Wq      = (const float*)d_in[2];
    const float* Wk      = (const float*)d_in[3];
    const float* Wv      = (const float*)d_in[4];
    const float* Wi      = (const float*)d_in[5];
    const float* bi      = (const float*)d_in[6];
    const float* Wf      = (const float*)d_in[7];
    const float* bf_     = (const float*)d_in[8];
    const float* mh_w    = (const float*)d_in[9];
    const float* Wog     = (const float*)d_in[10];
    const float* Wout    = (const float*)d_in[11];
    const float* norm2_w = (const float*)d_in[12];
    const float* W_up    = (const float*)d_in[13];
    const float* W_gate  = (const float*)d_in[14];
    const float* W_down  = (const float*)d_in[15];
    const float* final_w = (const float*)d_in[16];
    float* out = (float*)d_out;

    float* x   = SYMF(g_x);
    float* qb  = SYMF(g_q);
    float* kb  = SYMF(g_k);
    float* vb  = SYMF(g_v);
    float* ogb = SYMF(g_og);
    float* ifb = SYMF(g_if);
    float* gb  = SYMF(g_gate);
    float* ub  = SYMF(g_up);
    bf16* xnh  = SYMB(g_xn_h),  *xnl  = SYMB(g_xn_l);
    bf16* hvh  = SYMB(g_hv_h),  *hvl  = SYMB(g_hv_l);
    bf16* acth = SYMB(g_act_h), *actl = SYMB(g_act_l);

    bf16* wqh = SYMB(w_q_h),  *wql = SYMB(w_q_l);
    bf16* wkh = SYMB(w_k_h),  *wkl = SYMB(w_k_l);
    bf16* wvh = SYMB(w_v_h),  *wvl = SYMB(w_v_l);
    bf16* wogh= SYMB(w_og_h), *wogl= SYMB(w_og_l);
    bf16* woh = SYMB(w_o_h),  *wol = SYMB(w_o_l);
    bf16* wgh = SYMB(w_g_h),  *wgl = SYMB(w_g_l);
    bf16* wuh = SYMB(w_u_h),  *wul = SYMB(w_u_l);
    bf16* wdh = SYMB(w_d_h),  *wdl = SYMB(w_d_l);
    bf16* wifh= SYMB(w_if_h), *wifl= SYMB(w_if_l);

    // launch #1: x = u
    copy_kernel<<<(NTOK * HDIM / 4 + 255) / 256, 256>>>(u, x, NTOK * HDIM / 4);

    // launch #2: split FDIM-sized weights (Wg, Wu, Wd) in one go
    {
        SplitDesc sd;
        sd.nseg = 3;
        // tiles per seg: Wg (K=512,N=1408): 44*16=704; Wu: 704; Wd (K=1408,N=512): 16*44=704
        sd.seg[0] = { W_gate, wgh, wgl, HDIM, FDIM, 0    };
        sd.seg[1] = { W_up,   wuh, wul, HDIM, FDIM, 704  };
        sd.seg[2] = { W_down, wdh, wdl, FDIM, HDIM, 1408 };
        dim3 grid(2112, 1, LAYERS);
        split_transpose_multi_kernel<<<grid, dim3(32, 8)>>>(sd);
    }
    // launch #3: split HDIM-sized weights (Wq, Wk, Wv, Wog, Wout)
    {
        SplitDesc sd;
        sd.nseg = 5;
        // tiles: Wq/Wk (K=512,N=256): 8*16=128; Wv/Wog (512,512): 256; Wout (512,512): 256
        sd.seg[0] = { Wq,   wqh,  wql,  HDIM, QKDIM, 0   };
        sd.seg[1] = { Wk,   wkh,  wkl,  HDIM, QKDIM, 128 };
        sd.seg[2] = { Wv,   wvh,  wvl,  HDIM, VDIM,  256 };
        sd.seg[3] = { Wog,  wogh, wogl, HDIM, VDIM,  512 };
        sd.seg[4] = { Wout, woh,  wol,  VDIM, HDIM,  768 };
        dim3 grid(1024, 1, LAYERS);
        split_transpose_multi_kernel<<<grid, dim3(32, 8)>>>(sd);
    }
    // launch #4: pack Wi|Wf
    pack_wif_kernel<<<LAYERS * 64, 128>>>(Wi, Wf, wifh, wifl);

    for (int l = 0; l < LAYERS; ++l) {
        const size_t oqk = (size_t)l * QKDIM * HDIM;
        const size_t ov  = (size_t)l * VDIM * HDIM;
        const size_t of  = (size_t)l * FDIM * HDIM;
        const size_t oif = (size_t)l * 64 * HDIM;

        // --- mLSTM block ---
        rmsnorm_kernel<<<NTOK, 128>>>(x, norm1_w + l * HDIM,
                                      nullptr, xnh, xnl, 1);

        GemmDesc d1;            // q | k | v | og | if
        d1.nseg = 5;
        d1.seg[0] = { wqh + oqk,  wql + oqk,  qb,  nullptr, QKDIM, 0  };
        d1.seg[1] = { wkh + oqk,  wkl + oqk,  kb,  nullptr, QKDIM, 4  };
        d1.seg[2] = { wvh + ov,   wvl + ov,   vb,  nullptr, VDIM,  8  };
        d1.seg[3] = { wogh + ov,  wogl + ov,  ogb, nullptr, VDIM,  16 };
        d1.seg[4] = { wifh + oif, wifl + oif, ifb, nullptr, 64,    24 };
        gemm_multi(xnh, xnl, NTOK, HDIM, d1);

        mlstm_kernel<<<NTOK, 256>>>(qb, kb, vb, ogb, ifb,
                                    bi + l * NHEAD, bf_ + l * NHEAD,
                                    mh_w + (size_t)l * NHEAD * DHV, hvh, hvl);

        GemmDesc d2;            // x += hv @ Wout
        d2.nseg = 1;
        d2.seg[0] = { woh + ov, wol + ov, x, x, HDIM, 0 };
        gemm_multi(hvh, hvl, NTOK, VDIM, d2);

        // --- FFN block ---
        rmsnorm_kernel<<<NTOK, 128>>>(x, norm2_w + l * HDIM,
                                      nullptr, xnh, xnl, 1);

        GemmDesc d3;            // gate | up
        d3.nseg = 2;
        d3.seg[0] = { wgh + of, wgl + of, gb, nullptr, FDIM, 0  };
        d3.seg[1] = { wuh + of, wul + of, ub, nullptr, FDIM, 22 };
        gemm_multi(xnh, xnl, NTOK, HDIM, d3);

        silu_mul_kernel<<<(NTOK * FDIM / 4 + 255) / 256, 256>>>(
            gb, ub, acth, actl, NTOK * FDIM / 4);

        GemmDesc d4;            // x += act @ W_down
        d4.nseg = 1;
        d4.seg[0] = { wdh + (size_t)l * HDIM * FDIM,
                      wdl + (size_t)l * HDIM * FDIM, x, x, HDIM, 0 };
        gemm_multi(acth, actl, NTOK, FDIM, d4);
    }

    rmsnorm_kernel<<<NTOK, 128>>>(x, final_w, out, nullptr, nullptr, 0);
}

// round 14
// speedup vs baseline: 1.1575x; 1.0562x over previous
#include <cuda_runtime.h>
#include <cuda_bf16.h>
#include <cstdint>

// ---------------------------------------------------------------------------
// Problem constants
// ---------------------------------------------------------------------------
#define LAYERS 4
#define HDIM   512
#define NHEAD  8
#define DHQK   32
#define DHV    64
#define QKDIM  (NHEAD * DHQK)   // 256
#define VDIM   (NHEAD * DHV)    // 512
#define FDIM   1408
#define NTOK   2048              // B*P = 8*256
#define CAPV   15.0f
#define EPSV   1e-6f

typedef __nv_bfloat16  bf16;
typedef __nv_bfloat162 bf162;

// ---------------------------------------------------------------------------
// Device scratch (static: no allocation allowed)
// ---------------------------------------------------------------------------
__device__ float g_x   [NTOK * HDIM];
__device__ float g_q   [NTOK * QKDIM];
__device__ float g_k   [NTOK * QKDIM];
__device__ float g_v   [NTOK * VDIM];
__device__ float g_og  [NTOK * VDIM];
__device__ float g_if  [NTOK * 64];

// bf16 hi/lo split activations (GEMM A-operands, [M][K])
__device__ bf16 g_xn_h [NTOK * HDIM];
__device__ bf16 g_xn_l [NTOK * HDIM];
__device__ bf16 g_hv_h [NTOK * VDIM];
__device__ bf16 g_hv_l [NTOK * VDIM];
__device__ bf16 g_act_h[NTOK * FDIM];
__device__ bf16 g_act_l[NTOK * FDIM];

// bf16 hi/lo split weights, TRANSPOSED to [N][K] (GEMM B-operands)
__device__ bf16 w_q_h [LAYERS * QKDIM * HDIM];
__device__ bf16 w_q_l [LAYERS * QKDIM * HDIM];
__device__ bf16 w_k_h [LAYERS * QKDIM * HDIM];
__device__ bf16 w_k_l [LAYERS * QKDIM * HDIM];
__device__ bf16 w_v_h [LAYERS * VDIM * HDIM];
__device__ bf16 w_v_l [LAYERS * VDIM * HDIM];
__device__ bf16 w_og_h[LAYERS * VDIM * HDIM];
__device__ bf16 w_og_l[LAYERS * VDIM * HDIM];
__device__ bf16 w_o_h [LAYERS * HDIM * VDIM];
__device__ bf16 w_o_l [LAYERS * HDIM * VDIM];
__device__ bf16 w_g_h [LAYERS * FDIM * HDIM];
__device__ bf16 w_g_l [LAYERS * FDIM * HDIM];
__device__ bf16 w_u_h [LAYERS * FDIM * HDIM];
__device__ bf16 w_u_l [LAYERS * FDIM * HDIM];
__device__ bf16 w_d_h [LAYERS * HDIM * FDIM];
__device__ bf16 w_d_l [LAYERS * HDIM * FDIM];
__device__ bf16 w_if_h[LAYERS * 64 * HDIM];
__device__ bf16 w_if_l[LAYERS * 64 * HDIM];

// ---------------------------------------------------------------------------
// Helpers
// ---------------------------------------------------------------------------
__device__ __forceinline__ float softcapf(float x) {
    return CAPV * tanhf(x * (1.0f / CAPV));
}
__device__ __forceinline__ float logsigf(float x) {
    return (x >= 0.0f) ? -log1pf(expf(-x)) : (x - log1pf(expf(x)));
}
__device__ __forceinline__ float sigmoidf_(float x) {
    return 1.0f / (1.0f + expf(-x));
}
__device__ __forceinline__ void cpasync16(uint32_t dst, const void* src) {
    asm volatile("cp.async.cg.shared.global [%0], [%1], 16;\n"
                 :: "r"(dst), "l"(src));
}
__device__ __forceinline__ void split_bf16(float v, bf16& h, bf16& l) {
    h = __float2bfloat16_rn(v);
    l = __float2bfloat16_rn(v - __bfloat162float(h));
}

#define MMA_BF16(acc, a0, a1, a2, a3, b0, b1)                                  \
    asm volatile(                                                              \
        "mma.sync.aligned.m16n8k16.row.col.f32.bf16.bf16.f32 "                 \
        "{%0,%1,%2,%3}, {%4,%5,%6,%7}, {%8,%9}, {%0,%1,%2,%3};\n"              \
        : "+f"(acc[0]), "+f"(acc[1]), "+f"(acc[2]), "+f"(acc[3])               \
        : "r"(a0), "r"(a1), "r"(a2), "r"(a3), "r"(b0), "r"(b1))

// ---------------------------------------------------------------------------
// Plain device copy
// ---------------------------------------------------------------------------
__global__ __launch_bounds__(256) void copy_kernel(
    const float* __restrict__ in, float* __restrict__ out, int n4)
{
    int i = blockIdx.x * blockDim.x + threadIdx.x;
    if (i < n4) reinterpret_cast<float4*>(out)[i] =
        reinterpret_cast<const float4*>(in)[i];
}

// ---------------------------------------------------------------------------
// Multi-segment weight transform: fp32 W[K][N] -> bf16 hi/lo transposed [N][K].
// ---------------------------------------------------------------------------
#define MAXWSEG 5
struct SplitSeg {
    const float* in;
    bf16* hi;
    bf16* lo;
    int K, N;
    int tstart;
};
struct SplitDesc {
    int nseg;
    SplitSeg seg[MAXWSEG];
};

__global__ __launch_bounds__(256) void split_transpose_multi_kernel(SplitDesc d)
{
    __shared__ float t[32][33];
    const int tile = blockIdx.x;
    int si = 0;
#pragma unroll
    for (int s = 1; s < MAXWSEG; ++s)
        if (s < d.nseg && tile >= d.seg[s].tstart) si = s;
    const SplitSeg& sg = d.seg[si];
    const int l = blockIdx.z;
    const float* in = sg.in + (size_t)l * sg.K * sg.N;
    bf16* hi = sg.hi + (size_t)l * sg.N * sg.K;
    bf16* lo = sg.lo + (size_t)l * sg.N * sg.K;

    const int tl   = tile - sg.tstart;
    const int ntn  = sg.N / 32;
    const int n0   = (tl % ntn) * 32;
    const int k0   = (tl / ntn) * 32;
    const int tx = threadIdx.x, ty = threadIdx.y;
#pragma unroll
    for (int j = 0; j < 4; ++j)
        t[ty + 8 * j][tx] = in[(size_t)(k0 + ty + 8 * j) * sg.N + n0 + tx];
    __syncthreads();
#pragma unroll
    for (int j = 0; j < 4; ++j) {
        float v = t[tx][ty + 8 * j];
        bf16 h, lv; split_bf16(v, h, lv);
        size_t o = (size_t)(n0 + ty + 8 * j) * sg.K + k0 + tx;
        hi[o] = h; lo[o] = lv;
    }
}

// ---------------------------------------------------------------------------
// Pack [Wi | Wf | zeros] -> transposed split [64][HDIM] per layer.
// ---------------------------------------------------------------------------
__global__ void pack_wif_kernel(const float* __restrict__ Wi,
                                const float* __restrict__ Wf,
                                bf16* __restrict__ hi, bf16* __restrict__ lo)
{
    const int l = blockIdx.x >> 6;
    const int n = blockIdx.x & 63;
    for (int k = threadIdx.x; k < HDIM; k += blockDim.x) {
        float val = 0.0f;
        if (n < NHEAD)          val = Wi[((size_t)l * HDIM + k) * NHEAD + n];
        else if (n < 2 * NHEAD) val = Wf[((size_t)l * HDIM + k) * NHEAD + (n - NHEAD)];
        bf16 h, lv; split_bf16(val, h, lv);
        size_t o = ((size_t)l * 64 + n) * HDIM + k;
        hi[o] = h; lo[o] = lv;
    }
}

// ---------------------------------------------------------------------------
// Multi-segment bf16x3 GEMM (proven R12 inner loop).
// C_s[M,N_s] = A[M,K] @ W_s[K,N_s] (+ Res_s)
// acc += ah*bl + al*bh + ah*bh  (fp32 accumulate)
// CTA 64x64x32, 128 threads (4 warps 2x2, warp 32x32), 2-stage cp.async.
// ---------------------------------------------------------------------------
#define MAXSEG 5
struct GemmSeg {
    const bf16*  Bh;
    const bf16*  Bl;
    float*       C;
    const float* Res;   // nullptr = no residual add
    int          N;
    int          nstart;
};
struct GemmDesc {
    int nseg;
    GemmSeg seg[MAXSEG];
};

#define BM 64
#define BN 64
#define BK 32
#define BKPH 40   // 80B rows: banks (20r)%32 distinct -> conflict-free

__global__ __launch_bounds__(128) void gemm_bf16x3_kernel(
    const bf16* __restrict__ Ahi, const bf16* __restrict__ Alo,
    int M, int K, GemmDesc d)
{
    __shared__ bf16 Ah[2][BM][BKPH];
    __shared__ bf16 Al[2][BM][BKPH];
    __shared__ bf16 Bh[2][BN][BKPH];   // [n][k]
    __shared__ bf16 Bl[2][BN][BKPH];

    const int nblk = blockIdx.x;
    int si = 0;
#pragma unroll
    for (int t = 1; t < MAXSEG; ++t)
        if (t < d.nseg && nblk >= d.seg[t].nstart) si = t;
    const bf16* __restrict__ SBh = d.seg[si].Bh;
    const bf16* __restrict__ SBl = d.seg[si].Bl;
    float*      __restrict__ C   = d.seg[si].C;
    const float* __restrict__ Res = d.seg[si].Res;
    const int N  = d.seg[si].N;
    const int n0 = (nblk - d.seg[si].nstart) * BN;
    const int m0 = blockIdx.y * BM;

    const int tid  = threadIdx.x;
    const int warp = tid >> 5;
    const int lane = tid & 31;
    const int wm   = (warp >> 1) * 32;
    const int wn   = (warp & 1) * 32;
    const int gid  = lane >> 2;
    const int tig  = lane & 3;

    int rrow[2], rc16[2];
    uint32_t ah_dst[2][2], al_dst[2][2], bh_dst[2][2], bl_dst[2][2];
#pragma unroll
    for (int it = 0; it < 2; ++it) {
        int idx = tid + it * 128;
        rrow[it] = idx >> 2;
        rc16[it] = idx & 3;
#pragma unroll
        for (int s = 0; s < 2; ++s) {
            ah_dst[s][it] = (uint32_t)__cvta_generic_to_shared(&Ah[s][rrow[it]][rc16[it] * 8]);
            al_dst[s][it] = (uint32_t)__cvta_generic_to_shared(&Al[s][rrow[it]][rc16[it] * 8]);
            bh_dst[s][it] = (uint32_t)__cvta_generic_to_shared(&Bh[s][rrow[it]][rc16[it] * 8]);
            bl_dst[s][it] = (uint32_t)__cvta_generic_to_shared(&Bl[s][rrow[it]][rc16[it] * 8]);
        }
    }

    float acc[2][4][4];
#pragma unroll
    for (int mt = 0; mt < 2; ++mt)
#pragma unroll
        for (int nt = 0; nt < 4; ++nt)
#pragma unroll
            for (int r = 0; r < 4; ++r) acc[mt][nt][r] = 0.0f;

    const int nk = K / BK;

#pragma unroll
    for (int it = 0; it < 2; ++it) {
        cpasync16(ah_dst[0][it], Ahi + (size_t)(m0 + rrow[it]) * K + rc16[it] * 8);
        cpasync16(al_dst[0][it], Alo + (size_t)(m0 + rrow[it]) * K + rc16[it] * 8);
        cpasync16(bh_dst[0][it], SBh + (size_t)(n0 + rrow[it]) * K + rc16[it] * 8);
        cpasync16(bl_dst[0][it], SBl + (size_t)(n0 + rrow[it]) * K + rc16[it] * 8);
    }
    asm volatile("cp.async.commit_group;\n");

    for (int kt = 0; kt < nk; ++kt) {
        const int cur = kt & 1;
        if (kt + 1 < nk) {
            const int nxt = cur ^ 1;
            const int koff = (kt + 1) * BK;
#pragma unroll
            for (int it = 0; it < 2; ++it) {
                cpasync16(ah_dst[nxt][it], Ahi + (size_t)(m0 + rrow[it]) * K + koff + rc16[it] * 8);
                cpasync16(al_dst[nxt][it], Alo + (size_t)(m0 + rrow[it]) * K + koff + rc16[it] * 8);
                cpasync16(bh_dst[nxt][it], SBh + (size_t)(n0 + rrow[it]) * K + koff + rc16[it] * 8);
                cpasync16(bl_dst[nxt][it], SBl + (size_t)(n0 + rrow[it]) * K + koff + rc16[it] * 8);
            }
            asm volatile("cp.async.commit_group;\n");
            asm volatile("cp.async.wait_group 1;\n");
        } else {
            asm volatile("cp.async.wait_group 0;\n");
        }
        __syncthreads();

#pragma unroll
        for (int kk = 0; kk < BK; kk += 16) {
            uint32_t ah[2][4], al[2][4], bh_[4][2], bl_[4][2];
#pragma unroll
            for (int mt = 0; mt < 2; ++mt) {
                int r = wm + mt * 16 + gid;
                ah[mt][0] = *(const uint32_t*)&Ah[cur][r    ][kk + 2 * tig];
                ah[mt][1] = *(const uint32_t*)&Ah[cur][r + 8][kk + 2 * tig];
                ah[mt][2] = *(const uint32_t*)&Ah[cur][r    ][kk + 2 * tig + 8];
                ah[mt][3] = *(const uint32_t*)&Ah[cur][r + 8][kk + 2 * tig + 8];
                al[mt][0] = *(const uint32_t*)&Al[cur][r    ][kk + 2 * tig];
                al[mt][1] = *(const uint32_t*)&Al[cur][r + 8][kk + 2 * tig];
                al[mt][2] = *(const uint32_t*)&Al[cur][r    ][kk + 2 * tig + 8];
                al[mt][3] = *(const uint32_t*)&Al[cur][r + 8][kk + 2 * tig + 8];
            }
#pragma unroll
            for (int nt = 0; nt < 4; ++nt) {
                int c = wn + nt * 8 + gid;
                bh_[nt][0] = *(const uint32_t*)&Bh[cur][c][kk + 2 * tig];
                bh_[nt][1] = *(const uint32_t*)&Bh[cur][c][kk + 2 * tig + 8];
                bl_[nt][0] = *(const uint32_t*)&Bl[cur][c][kk + 2 * tig];
                bl_[nt][1] = *(const uint32_t*)&Bl[cur][c][kk + 2 * tig + 8];
            }
#pragma unroll
            for (int mt = 0; mt < 2; ++mt)
#pragma unroll
                for (int nt = 0; nt < 4; ++nt) {
                    MMA_BF16(acc[mt][nt], ah[mt][0], ah[mt][1], ah[mt][2], ah[mt][3],
                             bl_[nt][0], bl_[nt][1]);
                    MMA_BF16(acc[mt][nt], al[mt][0], al[mt][1], al[mt][2], al[mt][3],
                             bh_[nt][0], bh_[nt][1]);
                    MMA_BF16(acc[mt][nt], ah[mt][0], ah[mt][1], ah[mt][2], ah[mt][3],
                             bh_[nt][0], bh_[nt][1]);
                }
        }
        __syncthreads();
    }

#pragma unroll
    for (int mt = 0; mt < 2; ++mt) {
#pragma unroll
        for (int nt = 0; nt < 4; ++nt) {
            int r0 = m0 + wm + mt * 16 + gid;
            int c  = n0 + wn + nt * 8 + tig * 2;
            float2 v0 = make_float2(acc[mt][nt][0], acc[mt][nt][1]);
            float2 v1 = make_float2(acc[mt][nt][2], acc[mt][nt][3]);
            if (Res != nullptr) {
                float2 r = *reinterpret_cast<const float2*>(Res + (size_t)r0 * N + c);
                v0.x += r.x; v0.y += r.y;
                r = *reinterpret_cast<const float2*>(Res + (size_t)(r0 + 8) * N + c);
                v1.x += r.x; v1.y += r.y;
            }
            *reinterpret_cast<float2*>(C + (size_t)r0 * N + c)       = v0;
            *reinterpret_cast<float2*>(C + (size_t)(r0 + 8) * N + c) = v1;
        }
    }
}

// ---------------------------------------------------------------------------
// Paired gate|up GEMM + fused SwiGLU epilogue.
// Each CTA computes BOTH gate and up 64x64 tiles (shared A smem), then
// act = silu(gate)*up, split to bf16 hi/lo, written to out_hi/out_lo [M][FDIM].
// Numerics identical to separate GEMMs + silu kernel (fp32 gmem roundtrip
// was value-exact). Dynamic smem: 2 stages x 6 tiles x 5120B = 61440B.
// ---------------------------------------------------------------------------
#define PST 30720   // per-stage bytes
#define PT  5120    // per-tile bytes (64 x 40 bf16)

__global__ __launch_bounds__(128) void gemm_paired_kernel(
    const bf16* __restrict__ Ahi, const bf16* __restrict__ Alo,
    const bf16* __restrict__ Bgh, const bf16* __restrict__ Bgl,
    const bf16* __restrict__ Buh, const bf16* __restrict__ Bul,
    bf16* __restrict__ out_hi, bf16* __restrict__ out_lo,
    int M, int K, int Nfull)
{
    extern __shared__ __align__(16) char sm[];
    // stage layout: Ah | Al | Bgh | Bgl | Buh | Bul
    const uint32_t smb = (uint32_t)__cvta_generic_to_shared(sm);

    const int n0 = blockIdx.x * BN;
    const int m0 = blockIdx.y * BM;

    const int tid  = threadIdx.x;
    const int warp = tid >> 5;
    const int lane = tid & 31;
    const int wm   = (warp >> 1) * 32;
    const int wn   = (warp & 1) * 32;
    const int gid  = lane >> 2;
    const int tig  = lane & 3;

    int rrow[2], rc16[2];
#pragma unroll
    for (int it = 0; it < 2; ++it) {
        int idx = tid + it * 128;
        rrow[it] = idx >> 2;
        rc16[it] = idx & 3;
    }

    float accg[2][4][4], accu[2][4][4];
#pragma unroll
    for (int mt = 0; mt < 2; ++mt)
#pragma unroll
        for (int nt = 0; nt < 4; ++nt)
#pragma unroll
            for (int r = 0; r < 4; ++r) { accg[mt][nt][r] = 0.0f; accu[mt][nt][r] = 0.0f; }

    const int nk = K / BK;

    auto load_stage = [&](int s, int koff) {
        const uint32_t sb = smb + s * PST;
#pragma unroll
        for (int it = 0; it < 2; ++it) {
            const uint32_t doff = (uint32_t)(rrow[it] * 80 + rc16[it] * 16);
            const size_t asrc = (size_t)(m0 + rrow[it]) * K + koff + rc16[it] * 8;
            const size_t bsrc = (size_t)(n0 + rrow[it]) * K + koff + rc16[it] * 8;
            cpasync16(sb + doff,            Ahi + asrc);
            cpasync16(sb + PT     + doff,   Alo + asrc);
            cpasync16(sb + 2 * PT + doff,   Bgh + bsrc);
            cpasync16(sb + 3 * PT + doff,   Bgl + bsrc);
            cpasync16(sb + 4 * PT + doff,   Buh + bsrc);
            cpasync16(sb + 5 * PT + doff,   Bul + bsrc);
        }
        asm volatile("cp.async.commit_group;\n");
    };

    load_stage(0, 0);

    for (int kt = 0; kt < nk; ++kt) {
        const int cur = kt & 1;
        if (kt + 1 < nk) {
            load_stage(cur ^ 1, (kt + 1) * BK);
            asm volatile("cp.async.wait_group 1;\n");
        } else {
            asm volatile("cp.async.wait_group 0;\n");
        }
        __syncthreads();

        const bf16* sA_h = (const bf16*)(sm + cur * PST);
        const bf16* sA_l = (const bf16*)(sm + cur * PST + PT);
        const bf16* sG_h = (const bf16*)(sm + cur * PST + 2 * PT);
        const bf16* sG_l = (const bf16*)(sm + cur * PST + 3 * PT);
        const bf16* sU_h = (const bf16*)(sm + cur * PST + 4 * PT);
        const bf16* sU_l = (const bf16*)(sm + cur * PST + 5 * PT);

#pragma unroll
        for (int kk = 0; kk < BK; kk += 16) {
            uint32_t ah[2][4], al[2][4];
#pragma unroll
            for (int mt = 0; mt < 2; ++mt) {
                int r = wm + mt * 16 + gid;
                ah[mt][0] = *(const uint32_t*)&sA_h[(r    ) * BKPH + kk + 2 * tig];
                ah[mt][1] = *(const uint32_t*)&sA_h[(r + 8) * BKPH + kk + 2 * tig];
                ah[mt][2] = *(const uint32_t*)&sA_h[(r    ) * BKPH + kk + 2 * tig + 8];
                ah[mt][3] = *(const uint32_t*)&sA_h[(r + 8) * BKPH + kk + 2 * tig + 8];
                al[mt][0] = *(const uint32_t*)&sA_l[(r    ) * BKPH + kk + 2 * tig];
                al[mt][1] = *(const uint32_t*)&sA_l[(r + 8) * BKPH + kk + 2 * tig];
                al[mt][2] = *(const uint32_t*)&sA_l[(r    ) * BKPH + kk + 2 * tig + 8];
                al[mt][3] = *(const uint32_t*)&sA_l[(r + 8) * BKPH + kk + 2 * tig + 8];
            }
            // gate B fragments + MMAs
            {
                uint32_t bh_[4][2], bl_[4][2];
#pragma unroll
                for (int nt = 0; nt < 4; ++nt) {
                    int c = wn + nt * 8 + gid;
                    bh_[nt][0] = *(const uint32_t*)&sG_h[c * BKPH + kk + 2 * tig];
                    bh_[nt][1] = *(const uint32_t*)&sG_h[c * BKPH + kk + 2 * tig + 8];
                    bl_[nt][0] = *(const uint32_t*)&sG_l[c * BKPH + kk + 2 * tig];
                    bl_[nt][1] = *(const uint32_t*)&sG_l[c * BKPH + kk + 2 * tig + 8];
                }
#pragma unroll
                for (int mt = 0; mt < 2; ++mt)
#pragma unroll
                    for (int nt = 0; nt < 4; ++nt) {
                        MMA_BF16(accg[mt][nt], ah[mt][0], ah[mt][1], ah[mt][2], ah[mt][3],
                                 bl_[nt][0], bl_[nt][1]);
                        MMA_BF16(accg[mt][nt], al[mt][0], al[mt][1], al[mt][2], al[mt][3],
                                 bh_[nt][0], bh_[nt][1]);
                        MMA_BF16(accg[mt][nt], ah[mt][0], ah[mt][1], ah[mt][2], ah[mt][3],
                                 bh_[nt][0], bh_[nt][1]);
                    }
            }
            // up B fragments + MMAs
            {
                uint32_t bh_[4][2], bl_[4][2];
#pragma unroll
                for (int nt = 0; nt < 4; ++nt) {
                    int c = wn + nt * 8 + gid;
                    bh_[nt][0] = *(const uint32_t*)&sU_h[c * BKPH + kk + 2 * tig];
                    bh_[nt][1] = *(const uint32_t*)&sU_h[c * BKPH + kk + 2 * tig + 8];
                    bl_[nt][0] = *(const uint32_t*)&sU_l[c * BKPH + kk + 2 * tig];
                    bl_[nt][1] = *(const uint32_t*)&sU_l[c * BKPH + kk + 2 * tig + 8];
                }
#pragma unroll
                for (int mt = 0; mt < 2; ++mt)
#pragma unroll
                    for (int nt = 0; nt < 4; ++nt) {
                        MMA_BF16(accu[mt][nt], ah[mt][0], ah[mt][1], ah[mt][2], ah[mt][3],
                                 bl_[nt][0], bl_[nt][1]);
                        MMA_BF16(accu[mt][nt], al[mt][0], al[mt][1], al[mt][2], al[mt][3],
                                 bh_[nt][0], bh_[nt][1]);
                        MMA_BF16(accu[mt][nt], ah[mt][0], ah[mt][1], ah[mt][2], ah[mt][3],
                                 bh_[nt][0], bh_[nt][1]);
                    }
            }
        }
        __syncthreads();
    }

    // fused SwiGLU epilogue: act = silu(gate)*up, split bf16 hi/lo
#pragma unroll
    for (int mt = 0; mt < 2; ++mt) {
#pragma unroll
        for (int nt = 0; nt < 4; ++nt) {
            int r0 = m0 + wm + mt * 16 + gid;
            int c  = n0 + wn + nt * 8 + tig * 2;
#pragma unroll
            for (int half = 0; half < 2; ++half) {       // rows r0, r0+8
                int rr = r0 + half * 8;
                float gv0 = accg[mt][nt][2 * half],     uv0 = accu[mt][nt][2 * half];
                float gv1 = accg[mt][nt][2 * half + 1], uv1 = accu[mt][nt][2 * half + 1];
                float a0 = gv0 * sigmoidf_(gv0) * uv0;
                float a1 = gv1 * sigmoidf_(gv1) * uv1;
                bf16 h0, l0, h1, l1;
                split_bf16(a0, h0, l0);
                split_bf16(a1, h1, l1);
                size_t o = (size_t)rr * Nfull + c;
                *reinterpret_cast<bf162*>(out_hi + o) = __halves2bfloat162(h0, h1);
                *reinterpret_cast<bf162*>(out_lo + o) = __halves2bfloat162(l0, l1);
            }
        }
    }
}

// ---------------------------------------------------------------------------
// RMSNorm (H=512, block=128). split!=0: write bf16 hi/lo; else fp32 out.
// ---------------------------------------------------------------------------
__global__ __launch_bounds__(128) void rmsnorm_kernel(
    const float* __restrict__ x, const float* __restrict__ w,
    float* __restrict__ out, bf16* __restrict__ out_hi,
    bf16* __restrict__ out_lo, int split)
{
    const int row = blockIdx.x, tid = threadIdx.x;
    float4 v = reinterpret_cast<const float4*>(x + (size_t)row * HDIM)[tid];
    float ss = v.x * v.x + v.y * v.y + v.z * v.z + v.w * v.w;
#pragma unroll
    for (int o = 16; o; o >>= 1) ss += __shfl_xor_sync(0xffffffffu, ss, o);
    __shared__ float sred[4];
    if ((tid & 31) == 0) sred[tid >> 5] = ss;
    __syncthreads();
    float tot = sred[0] + sred[1] + sred[2] + sred[3];
    float inv = rsqrtf(tot * (1.0f / (float)HDIM) + EPSV);
    float4 wv = reinterpret_cast<const float4*>(w)[tid];
    float4 o4 = make_float4(v.x * inv * wv.x, v.y * inv * wv.y,
                            v.z * inv * wv.z, v.w * inv * wv.w);
    if (split) {
        bf16 hx, lx, hy, ly, hz, lz, hw, lw;
        split_bf16(o4.x, hx, lx); split_bf16(o4.y, hy, ly);
        split_bf16(o4.z, hz, lz); split_bf16(o4.w, hw, lw);
        bf162* oh = reinterpret_cast<bf162*>(out_hi + (size_t)row * HDIM);
        bf162* ol = reinterpret_cast<bf162*>(out_lo + (size_t)row * HDIM);
        oh[tid * 2]     = __halves2bfloat162(hx, hy);
        oh[tid * 2 + 1] = __halves2bfloat162(hz, hw);
        ol[tid * 2]     = __halves2bfloat162(lx, ly);
        ol[tid * 2 + 1] = __halves2bfloat162(lz, lw);
    } else {
        reinterpret_cast<float4*>(out + (size_t)row * HDIM)[tid] = o4;
    }
}

// ---------------------------------------------------------------------------
// mLSTM step (zero state) + per-head RMSNorm + output gate.
// ---------------------------------------------------------------------------
__global__ __launch_bounds__(256) void mlstm_kernel(
    const float* __restrict__ q, const float* __restrict__ k,
    const float* __restrict__ v, const float* __restrict__ ogp,
    const float* __restrict__ ifp,
    const float* __restrict__ bi, const float* __restrict__ bf,
    const float* __restrict__ mhw,
    bf16* __restrict__ hv_hi, bf16* __restrict__ hv_lo)
{
    const int t = blockIdx.x;
    const int h = threadIdx.x >> 5;
    const int lane = threadIdx.x & 31;

    float ip = softcapf(ifp[(size_t)t * 64 + h]      + bi[h]);
    float fp = softcapf(ifp[(size_t)t * 64 + 8 + h]  + bf[h]);
    float flog = logsigf(fp);
    float m = fmaxf(flog, ip);
    float iact = expf(ip - m);

    float qd = q[(size_t)t * QKDIM + h * DHQK + lane];
    float kd = k[(size_t)t * QKDIM + h * DHQK + lane];
    float s = qd * kd;
#pragma unroll
    for (int o = 16; o; o >>= 1) s += __shfl_xor_sync(0xffffffffu, s, o);
    s *= 0.17677669529663687f;  // 32^-0.5

    float qn = iact * s;
    float denom = fmaxf(fabsf(qn), expf(-m)) + EPSV;
    float c = iact * s / denom;

    const int base = t * VDIM + h * DHV;
    float v0 = v[base + lane], v1 = v[base + 32 + lane];
    float h0 = c * v0, h1 = c * v1;

    float ms = h0 * h0 + h1 * h1;
#pragma unroll
    for (int o = 16; o; o >>= 1) ms += __shfl_xor_sync(0xffffffffu, ms, o);
    float inv = rsqrtf(ms * (1.0f / (float)DHV) + EPSV);

    float w0 = mhw[h * DHV + lane],      w1 = mhw[h * DHV + 32 + lane];
    float g0 = sigmoidf_(ogp[base + lane]);
    float g1 = sigmoidf_(ogp[base + 32 + lane]);
    float r0 = h0 * inv * w0 * g0;
    float r1 = h1 * inv * w1 * g1;
    bf16 rh, rl;
    split_bf16(r0, rh, rl);
    hv_hi[base + lane] = rh;           hv_lo[base + lane] = rl;
    split_bf16(r1, rh, rl);
    hv_hi[base + 32 + lane] = rh;      hv_lo[base + 32 + lane] = rl;
}

// ---------------------------------------------------------------------------
// Host launcher
// ---------------------------------------------------------------------------
static inline void* sym_addr_v(const void* sym) {
    void* p = nullptr;
    cudaGetSymbolAddress(&p, sym);
    return p;
}
#define SYMF(s)  ((float*)sym_addr_v(s))
#define SYMB(s)  ((bf16*)sym_addr_v(s))

static inline void gemm_multi(const bf16* Ahi, const bf16* Alo,
                              int M, int K, const GemmDesc& d) {
    int nb = d.seg[d.nseg - 1].nstart + d.seg[d.nseg - 1].N / BN;
    dim3 grid(nb, M / BM);
    gemm_bf16x3_kernel<<<grid, 128>>>(Ahi, Alo, M, K, d);
}

extern "C" void kernel_launch(void* const* d_in, const int* in_sizes, int n_in,
                              void* d_out, int out_size)
{
    (void)in_sizes; (void)n_in; (void)out_size;
    const float* u       = (const float*)d_in[0];
    const float* norm1_w = (const float*)d_in[1];
    const float* Wq      = (const float*)d_in[2];
    const float* Wk      = (const float*)d_in[3];
    const float* Wv      = (const float*)d_in[4];
    const float* Wi      = (const float*)d_in[5];
    const float* bi      = (const float*)d_in[6];
    const float* Wf      = (const float*)d_in[7];
    const float* bf_     = (const float*)d_in[8];
    const float* mh_w    = (const float*)d_in[9];
    const float* Wog     = (const float*)d_in[10];
    const float* Wout    = (const float*)d_in[11];
    const float* norm2_w = (const float*)d_in[12];
    const float* W_up    = (const float*)d_in[13];
    const float* W_gate  = (const float*)d_in[14];
    const float* W_down  = (const float*)d_in[15];
    const float* final_w = (const float*)d_in[16];
    float* out = (float*)d_out;

    cudaFuncSetAttribute(gemm_paired_kernel,
                         cudaFuncAttributeMaxDynamicSharedMemorySize, 2 * PST);

    float* x   = SYMF(g_x);
    float* qb  = SYMF(g_q);
    float* kb  = SYMF(g_k);
    float* vb  = SYMF(g_v);
    float* ogb = SYMF(g_og);
    float* ifb = SYMF(g_if);
    bf16* xnh  = SYMB(g_xn_h),  *xnl  = SYMB(g_xn_l);
    bf16* hvh  = SYMB(g_hv_h),  *hvl  = SYMB(g_hv_l);
    bf16* acth = SYMB(g_act_h), *actl = SYMB(g_act_l);

    bf16* wqh = SYMB(w_q_h),  *wql = SYMB(w_q_l);
    bf16* wkh = SYMB(w_k_h),  *wkl = SYMB(w_k_l);
    bf16* wvh = SYMB(w_v_h),  *wvl = SYMB(w_v_l);
    bf16* wogh= SYMB(w_og_h), *wogl= SYMB(w_og_l);
    bf16* woh = SYMB(w_o_h),  *wol = SYMB(w_o_l);
    bf16* wgh = SYMB(w_g_h),  *wgl = SYMB(w_g_l);
    bf16* wuh = SYMB(w_u_h),  *wul = SYMB(w_u_l);
    bf16* wdh = SYMB(w_d_h),  *wdl = SYMB(w_d_l);
    bf16* wifh= SYMB(w_if_h), *wifl= SYMB(w_if_l);

    copy_kernel<<<(NTOK * HDIM / 4 + 255) / 256, 256>>>(u, x, NTOK * HDIM / 4);

    {
        SplitDesc sd;
        sd.nseg = 3;
        sd.seg[0] = { W_gate, wgh, wgl, HDIM, FDIM, 0    };
        sd.seg[1] = { W_up,   wuh, wul, HDIM, FDIM, 704  };
        sd.seg[2] = { W_down, wdh, wdl, FDIM, HDIM, 1408 };
        dim3 grid(2112, 1, LAYERS);
        split_transpose_multi_kernel<<<grid, dim3(32, 8)>>>(sd);
    }
    {
        SplitDesc sd;
        sd.nseg = 5;
        sd.seg[0] = { Wq,   wqh,  wql,  HDIM, QKDIM, 0   };
        sd.seg[1] = { Wk,   wkh,  wkl,  HDIM, QKDIM, 128 };
        sd.seg[2] = { Wv,   wvh,  wvl,  HDIM, VDIM,  256 };
        sd.seg[3] = { Wog,  wogh, wogl, HDIM, VDIM,  512 };
        sd.seg[4] = { Wout, woh,  wol,  VDIM, HDIM,  768 };
        dim3 grid(1024, 1, LAYERS);
        split_transpose_multi_kernel<<<grid, dim3(32, 8)>>>(sd);
    }
    pack_wif_kernel<<<LAYERS * 64, 128>>>(Wi, Wf, wifh, wifl);

    for (int l = 0; l < LAYERS; ++l) {
        const size_t oqk = (size_t)l * QKDIM * HDIM;
        const size_t ov  = (size_t)l * VDIM * HDIM;
        const size_t of  = (size_t)l * FDIM * HDIM;
        const size_t oif = (size_t)l * 64 * HDIM;

        // --- mLSTM block ---
        rmsnorm_kernel<<<NTOK, 128>>>(x, norm1_w + l * HDIM,
                                      nullptr, xnh, xnl, 1);

        GemmDesc d1;            // q | k | v | og | if
        d1.nseg = 5;
        d1.seg[0] = { wqh + oqk,  wql + oqk,  qb,  nullptr, QKDIM, 0  };
        d1.seg[1] = { wkh + oqk,  wkl + oqk,  kb,  nullptr, QKDIM, 4  };
        d1.seg[2] = { wvh + ov,   wvl + ov,   vb,  nullptr, VDIM,  8  };
        d1.seg[3] = { wogh + ov,  wogl + ov,  ogb, nullptr, VDIM,  16 };
        d1.seg[4] = { wifh + oif, wifl + oif, ifb, nullptr, 64,    24 };
        gemm_multi(xnh, xnl, NTOK, HDIM, d1);

        mlstm_kernel<<<NTOK, 256>>>(qb, kb, vb, ogb, ifb,
                                    bi + l * NHEAD, bf_ + l * NHEAD,
                                    mh_w + (size_t)l * NHEAD * DHV, hvh, hvl);

        GemmDesc d2;            // x += hv @ Wout
        d2.nseg = 1;
        d2.seg[0] = { woh + ov, wol + ov, x, x, HDIM, 0 };
        gemm_multi(hvh, hvl, NTOK, VDIM, d2);

        // --- FFN block ---
        rmsnorm_kernel<<<NTOK, 128>>>(x, norm2_w + l * HDIM,
                                      nullptr, xnh, xnl, 1);

        // paired gate|up GEMM with fused SwiGLU epilogue -> act (split bf16)
        {
            dim3 grid(FDIM / BN, NTOK / BM);
            gemm_paired_kernel<<<grid, 128, 2 * PST>>>(
                xnh, xnl, wgh + of, wgl + of, wuh + of, wul + of,
                acth, actl, NTOK, HDIM, FDIM);
        }

        GemmDesc d4;            // x += act @ W_down
        d4.nseg = 1;
        d4.seg[0] = { wdh + (size_t)l * HDIM * FDIM,
                      wdl + (size_t)l * HDIM * FDIM, x, x, HDIM, 0 };
        gemm_multi(acth, actl, NTOK, FDIM, d4);
    }

    rmsnorm_kernel<<<NTOK, 128>>>(x, final_w, out, nullptr, nullptr, 0);
}

// round 16
// speedup vs baseline: 1.1880x; 1.0263x over previous
#include <cuda_runtime.h>
#include <cuda_bf16.h>
#include <cstdint>

// ---------------------------------------------------------------------------
// Problem constants
// ---------------------------------------------------------------------------
#define LAYERS 4
#define HDIM   512
#define NHEAD  8
#define DHQK   32
#define DHV    64
#define QKDIM  (NHEAD * DHQK)   // 256
#define VDIM   (NHEAD * DHV)    // 512
#define FDIM   1408
#define NTOK   2048              // B*P = 8*256
#define CAPV   15.0f
#define EPSV   1e-6f

typedef __nv_bfloat16  bf16;
typedef __nv_bfloat162 bf162;

// ---------------------------------------------------------------------------
// Device scratch (static: no allocation allowed)
// ---------------------------------------------------------------------------
__device__ float g_x   [NTOK * HDIM];
__device__ float g_q   [NTOK * QKDIM];
__device__ float g_k   [NTOK * QKDIM];
__device__ float g_v   [NTOK * VDIM];
__device__ float g_og  [NTOK * VDIM];
__device__ float g_if  [NTOK * 64];
__device__ float g_p0  [NTOK * HDIM];   // split-K partials
__device__ float g_p1  [NTOK * HDIM];

// bf16 hi/lo split activations (GEMM A-operands, [M][K])
__device__ bf16 g_xn_h [NTOK * HDIM];
__device__ bf16 g_xn_l [NTOK * HDIM];
__device__ bf16 g_hv_h [NTOK * VDIM];
__device__ bf16 g_hv_l [NTOK * VDIM];
__device__ bf16 g_act_h[NTOK * FDIM];
__device__ bf16 g_act_l[NTOK * FDIM];

// bf16 hi/lo split weights, TRANSPOSED to [N][K] (GEMM B-operands)
__device__ bf16 w_q_h [LAYERS * QKDIM * HDIM];
__device__ bf16 w_q_l [LAYERS * QKDIM * HDIM];
__device__ bf16 w_k_h [LAYERS * QKDIM * HDIM];
__device__ bf16 w_k_l [LAYERS * QKDIM * HDIM];
__device__ bf16 w_v_h [LAYERS * VDIM * HDIM];
__device__ bf16 w_v_l [LAYERS * VDIM * HDIM];
__device__ bf16 w_og_h[LAYERS * VDIM * HDIM];
__device__ bf16 w_og_l[LAYERS * VDIM * HDIM];
__device__ bf16 w_o_h [LAYERS * HDIM * VDIM];
__device__ bf16 w_o_l [LAYERS * HDIM * VDIM];
__device__ bf16 w_g_h [LAYERS * FDIM * HDIM];
__device__ bf16 w_g_l [LAYERS * FDIM * HDIM];
__device__ bf16 w_u_h [LAYERS * FDIM * HDIM];
__device__ bf16 w_u_l [LAYERS * FDIM * HDIM];
__device__ bf16 w_d_h [LAYERS * HDIM * FDIM];
__device__ bf16 w_d_l [LAYERS * HDIM * FDIM];
__device__ bf16 w_if_h[LAYERS * 64 * HDIM];
__device__ bf16 w_if_l[LAYERS * 64 * HDIM];

// ---------------------------------------------------------------------------
// Helpers
// ---------------------------------------------------------------------------
__device__ __forceinline__ float softcapf(float x) {
    return CAPV * tanhf(x * (1.0f / CAPV));
}
__device__ __forceinline__ float logsigf(float x) {
    return (x >= 0.0f) ? -log1pf(expf(-x)) : (x - log1pf(expf(x)));
}
__device__ __forceinline__ float sigmoidf_(float x) {
    return 1.0f / (1.0f + expf(-x));
}
__device__ __forceinline__ void cpasync16(uint32_t dst, const void* src) {
    asm volatile("cp.async.cg.shared.global [%0], [%1], 16;\n"
                 :: "r"(dst), "l"(src));
}
__device__ __forceinline__ void split_bf16(float v, bf16& h, bf16& l) {
    h = __float2bfloat16_rn(v);
    l = __float2bfloat16_rn(v - __bfloat162float(h));
}

#define MMA_BF16(acc, a0, a1, a2, a3, b0, b1)                                  \
    asm volatile(                                                              \
        "mma.sync.aligned.m16n8k16.row.col.f32.bf16.bf16.f32 "                 \
        "{%0,%1,%2,%3}, {%4,%5,%6,%7}, {%8,%9}, {%0,%1,%2,%3};\n"              \
        : "+f"(acc[0]), "+f"(acc[1]), "+f"(acc[2]), "+f"(acc[3])               \
        : "r"(a0), "r"(a1), "r"(a2), "r"(a3), "r"(b0), "r"(b1))

// ---------------------------------------------------------------------------
// Plain device copy
// ---------------------------------------------------------------------------
__global__ __launch_bounds__(256) void copy_kernel(
    const float* __restrict__ in, float* __restrict__ out, int n4)
{
    int i = blockIdx.x * blockDim.x + threadIdx.x;
    if (i < n4) reinterpret_cast<float4*>(out)[i] =
        reinterpret_cast<const float4*>(in)[i];
}

// ---------------------------------------------------------------------------
// Multi-segment weight transform: fp32 W[K][N] -> bf16 hi/lo transposed [N][K].
// ---------------------------------------------------------------------------
#define MAXWSEG 5
struct SplitSeg {
    const float* in;
    bf16* hi;
    bf16* lo;
    int K, N;
    int tstart;
};
struct SplitDesc {
    int nseg;
    SplitSeg seg[MAXWSEG];
};

__global__ __launch_bounds__(256) void split_transpose_multi_kernel(SplitDesc d)
{
    __shared__ float t[32][33];
    const int tile = blockIdx.x;
    int si = 0;
#pragma unroll
    for (int s = 1; s < MAXWSEG; ++s)
        if (s < d.nseg && tile >= d.seg[s].tstart) si = s;
    const SplitSeg& sg = d.seg[si];
    const int l = blockIdx.z;
    const float* in = sg.in + (size_t)l * sg.K * sg.N;
    bf16* hi = sg.hi + (size_t)l * sg.N * sg.K;
    bf16* lo = sg.lo + (size_t)l * sg.N * sg.K;

    const int tl   = tile - sg.tstart;
    const int ntn  = sg.N / 32;
    const int n0   = (tl % ntn) * 32;
    const int k0   = (tl / ntn) * 32;
    const int tx = threadIdx.x, ty = threadIdx.y;
#pragma unroll
    for (int j = 0; j < 4; ++j)
        t[ty + 8 * j][tx] = in[(size_t)(k0 + ty + 8 * j) * sg.N + n0 + tx];
    __syncthreads();
#pragma unroll
    for (int j = 0; j < 4; ++j) {
        float v = t[tx][ty + 8 * j];
        bf16 h, lv; split_bf16(v, h, lv);
        size_t o = (size_t)(n0 + ty + 8 * j) * sg.K + k0 + tx;
        hi[o] = h; lo[o] = lv;
    }
}

// ---------------------------------------------------------------------------
// Pack [Wi | Wf | zeros] -> transposed split [64][HDIM] per layer.
// ---------------------------------------------------------------------------
__global__ void pack_wif_kernel(const float* __restrict__ Wi,
                                const float* __restrict__ Wf,
                                bf16* __restrict__ hi, bf16* __restrict__ lo)
{
    const int l = blockIdx.x >> 6;
    const int n = blockIdx.x & 63;
    for (int k = threadIdx.x; k < HDIM; k += blockDim.x) {
        float val = 0.0f;
        if (n < NHEAD)          val = Wi[((size_t)l * HDIM + k) * NHEAD + n];
        else if (n < 2 * NHEAD) val = Wf[((size_t)l * HDIM + k) * NHEAD + (n - NHEAD)];
        bf16 h, lv; split_bf16(val, h, lv);
        size_t o = ((size_t)l * 64 + n) * HDIM + k;
        hi[o] = h; lo[o] = lv;
    }
}

// ---------------------------------------------------------------------------
// Multi-segment bf16x3 GEMM with per-segment K-range (split-K support).
// C_s[M,N_s] = A[M, koff:koff+ksz] @ W_s[koff:koff+ksz, N_s] (+ Res_s)
// acc += ah*bl + al*bh + ah*bh  (fp32 accumulate)
// CTA 64x64x32, 128 threads (4 warps 2x2, warp 32x32), 2-stage cp.async.
// ---------------------------------------------------------------------------
#define MAXSEG 5
struct GemmSeg {
    const bf16*  Bh;
    const bf16*  Bl;
    float*       C;
    const float* Res;   // nullptr = no residual add
    int          N;
    int          nstart;
    int          koff;  // K-range start
    int          ksz;   // K-range size (multiple of BK)
};
struct GemmDesc {
    int nseg;
    GemmSeg seg[MAXSEG];
};

#define BM 64
#define BN 64
#define BK 32
#define BKPH 40   // 80B rows: banks (20r)%32 distinct -> conflict-free

__global__ __launch_bounds__(128) void gemm_bf16x3_kernel(
    const bf16* __restrict__ Ahi, const bf16* __restrict__ Alo,
    int M, int K, GemmDesc d)
{
    __shared__ bf16 Ah[2][BM][BKPH];
    __shared__ bf16 Al[2][BM][BKPH];
    __shared__ bf16 Bh[2][BN][BKPH];   // [n][k]
    __shared__ bf16 Bl[2][BN][BKPH];

    const int nblk = blockIdx.x;
    int si = 0;
#pragma unroll
    for (int t = 1; t < MAXSEG; ++t)
        if (t < d.nseg && nblk >= d.seg[t].nstart) si = t;
    const bf16* __restrict__ SBh = d.seg[si].Bh;
    const bf16* __restrict__ SBl = d.seg[si].Bl;
    float*      __restrict__ C   = d.seg[si].C;
    const float* __restrict__ Res = d.seg[si].Res;
    const int N   = d.seg[si].N;
    const int n0  = (nblk - d.seg[si].nstart) * BN;
    const int kof = d.seg[si].koff;
    const int nk  = d.seg[si].ksz / BK;
    const int m0  = blockIdx.y * BM;

    const int tid  = threadIdx.x;
    const int warp = tid >> 5;
    const int lane = tid & 31;
    const int wm   = (warp >> 1) * 32;
    const int wn   = (warp & 1) * 32;
    const int gid  = lane >> 2;
    const int tig  = lane & 3;

    int rrow[2], rc16[2];
    uint32_t ah_dst[2][2], al_dst[2][2], bh_dst[2][2], bl_dst[2][2];
#pragma unroll
    for (int it = 0; it < 2; ++it) {
        int idx = tid + it * 128;
        rrow[it] = idx >> 2;
        rc16[it] = idx & 3;
#pragma unroll
        for (int s = 0; s < 2; ++s) {
            ah_dst[s][it] = (uint32_t)__cvta_generic_to_shared(&Ah[s][rrow[it]][rc16[it] * 8]);
            al_dst[s][it] = (uint32_t)__cvta_generic_to_shared(&Al[s][rrow[it]][rc16[it] * 8]);
            bh_dst[s][it] = (uint32_t)__cvta_generic_to_shared(&Bh[s][rrow[it]][rc16[it] * 8]);
            bl_dst[s][it] = (uint32_t)__cvta_generic_to_shared(&Bl[s][rrow[it]][rc16[it] * 8]);
        }
    }

    float acc[2][4][4];
#pragma unroll
    for (int mt = 0; mt < 2; ++mt)
#pragma unroll
        for (int nt = 0; nt < 4; ++nt)
#pragma unroll
            for (int r = 0; r < 4; ++r) acc[mt][nt][r] = 0.0f;

#pragma unroll
    for (int it = 0; it < 2; ++it) {
        cpasync16(ah_dst[0][it], Ahi + (size_t)(m0 + rrow[it]) * K + kof + rc16[it] * 8);
        cpasync16(al_dst[0][it], Alo + (size_t)(m0 + rrow[it]) * K + kof + rc16[it] * 8);
        cpasync16(bh_dst[0][it], SBh + (size_t)(n0 + rrow[it]) * K + kof + rc16[it] * 8);
        cpasync16(bl_dst[0][it], SBl + (size_t)(n0 + rrow[it]) * K + kof + rc16[it] * 8);
    }
    asm volatile("cp.async.commit_group;\n");

    for (int kt = 0; kt < nk; ++kt) {
        const int cur = kt & 1;
        if (kt + 1 < nk) {
            const int nxt = cur ^ 1;
            const int koff = kof + (kt + 1) * BK;
#pragma unroll
            for (int it = 0; it < 2; ++it) {
                cpasync16(ah_dst[nxt][it], Ahi + (size_t)(m0 + rrow[it]) * K + koff + rc16[it] * 8);
                cpasync16(al_dst[nxt][it], Alo + (size_t)(m0 + rrow[it]) * K + koff + rc16[it] * 8);
                cpasync16(bh_dst[nxt][it], SBh + (size_t)(n0 + rrow[it]) * K + koff + rc16[it] * 8);
                cpasync16(bl_dst[nxt][it], SBl + (size_t)(n0 + rrow[it]) * K + koff + rc16[it] * 8);
            }
            asm volatile("cp.async.commit_group;\n");
            asm volatile("cp.async.wait_group 1;\n");
        } else {
            asm volatile("cp.async.wait_group 0;\n");
        }
        __syncthreads();

#pragma unroll
        for (int kk = 0; kk < BK; kk += 16) {
            uint32_t ah[2][4], al[2][4], bh_[4][2], bl_[4][2];
#pragma unroll
            for (int mt = 0; mt < 2; ++mt) {
                int r = wm + mt * 16 + gid;
                ah[mt][0] = *(const uint32_t*)&Ah[cur][r    ][kk + 2 * tig];
                ah[mt][1] = *(const uint32_t*)&Ah[cur][r + 8][kk + 2 * tig];
                ah[mt][2] = *(const uint32_t*)&Ah[cur][r    ][kk + 2 * tig + 8];
                ah[mt][3] = *(const uint32_t*)&Ah[cur][r + 8][kk + 2 * tig + 8];
                al[mt][0] = *(const uint32_t*)&Al[cur][r    ][kk + 2 * tig];
                al[mt][1] = *(const uint32_t*)&Al[cur][r + 8][kk + 2 * tig];
                al[mt][2] = *(const uint32_t*)&Al[cur][r    ][kk + 2 * tig + 8];
                al[mt][3] = *(const uint32_t*)&Al[cur][r + 8][kk + 2 * tig + 8];
            }
#pragma unroll
            for (int nt = 0; nt < 4; ++nt) {
                int c = wn + nt * 8 + gid;
                bh_[nt][0] = *(const uint32_t*)&Bh[cur][c][kk + 2 * tig];
                bh_[nt][1] = *(const uint32_t*)&Bh[cur][c][kk + 2 * tig + 8];
                bl_[nt][0] = *(const uint32_t*)&Bl[cur][c][kk + 2 * tig];
                bl_[nt][1] = *(const uint32_t*)&Bl[cur][c][kk + 2 * tig + 8];
            }
#pragma unroll
            for (int mt = 0; mt < 2; ++mt)
#pragma unroll
                for (int nt = 0; nt < 4; ++nt) {
                    MMA_BF16(acc[mt][nt], ah[mt][0], ah[mt][1], ah[mt][2], ah[mt][3],
                             bl_[nt][0], bl_[nt][1]);
                    MMA_BF16(acc[mt][nt], al[mt][0], al[mt][1], al[mt][2], al[mt][3],
                             bh_[nt][0], bh_[nt][1]);
                    MMA_BF16(acc[mt][nt], ah[mt][0], ah[mt][1], ah[mt][2], ah[mt][3],
                             bh_[nt][0], bh_[nt][1]);
                }
        }
        __syncthreads();
    }

#pragma unroll
    for (int mt = 0; mt < 2; ++mt) {
#pragma unroll
        for (int nt = 0; nt < 4; ++nt) {
            int r0 = m0 + wm + mt * 16 + gid;
            int c  = n0 + wn + nt * 8 + tig * 2;
            float2 v0 = make_float2(acc[mt][nt][0], acc[mt][nt][1]);
            float2 v1 = make_float2(acc[mt][nt][2], acc[mt][nt][3]);
            if (Res != nullptr) {
                float2 r = *reinterpret_cast<const float2*>(Res + (size_t)r0 * N + c);
                v0.x += r.x; v0.y += r.y;
                r = *reinterpret_cast<const float2*>(Res + (size_t)(r0 + 8) * N + c);
                v1.x += r.x; v1.y += r.y;
            }
            *reinterpret_cast<float2*>(C + (size_t)r0 * N + c)       = v0;
            *reinterpret_cast<float2*>(C + (size_t)(r0 + 8) * N + c) = v1;
        }
    }
}

// ---------------------------------------------------------------------------
// Paired gate|up GEMM + fused SwiGLU epilogue.
// ---------------------------------------------------------------------------
#define PST 30720
#define PT  5120

__global__ __launch_bounds__(128) void gemm_paired_kernel(
    const bf16* __restrict__ Ahi, const bf16* __restrict__ Alo,
    const bf16* __restrict__ Bgh, const bf16* __restrict__ Bgl,
    const bf16* __restrict__ Buh, const bf16* __restrict__ Bul,
    bf16* __restrict__ out_hi, bf16* __restrict__ out_lo,
    int M, int K, int Nfull)
{
    extern __shared__ __align__(16) char sm[];
    const uint32_t smb = (uint32_t)__cvta_generic_to_shared(sm);

    const int n0 = blockIdx.x * BN;
    const int m0 = blockIdx.y * BM;

    const int tid  = threadIdx.x;
    const int warp = tid >> 5;
    const int lane = tid & 31;
    const int wm   = (warp >> 1) * 32;
    const int wn   = (warp & 1) * 32;
    const int gid  = lane >> 2;
    const int tig  = lane & 3;

    int rrow[2], rc16[2];
#pragma unroll
    for (int it = 0; it < 2; ++it) {
        int idx = tid + it * 128;
        rrow[it] = idx >> 2;
        rc16[it] = idx & 3;
    }

    float accg[2][4][4], accu[2][4][4];
#pragma unroll
    for (int mt = 0; mt < 2; ++mt)
#pragma unroll
        for (int nt = 0; nt < 4; ++nt)
#pragma unroll
            for (int r = 0; r < 4; ++r) { accg[mt][nt][r] = 0.0f; accu[mt][nt][r] = 0.0f; }

    const int nk = K / BK;

    auto load_stage = [&](int s, int koff) {
        const uint32_t sb = smb + s * PST;
#pragma unroll
        for (int it = 0; it < 2; ++it) {
            const uint32_t doff = (uint32_t)(rrow[it] * 80 + rc16[it] * 16);
            const size_t asrc = (size_t)(m0 + rrow[it]) * K + koff + rc16[it] * 8;
            const size_t bsrc = (size_t)(n0 + rrow[it]) * K + koff + rc16[it] * 8;
            cpasync16(sb + doff,            Ahi + asrc);
            cpasync16(sb + PT     + doff,   Alo + asrc);
            cpasync16(sb + 2 * PT + doff,   Bgh + bsrc);
            cpasync16(sb + 3 * PT + doff,   Bgl + bsrc);
            cpasync16(sb + 4 * PT + doff,   Buh + bsrc);
            cpasync16(sb + 5 * PT + doff,   Bul + bsrc);
        }
        asm volatile("cp.async.commit_group;\n");
    };

    load_stage(0, 0);

    for (int kt = 0; kt < nk; ++kt) {
        const int cur = kt & 1;
        if (kt + 1 < nk) {
            load_stage(cur ^ 1, (kt + 1) * BK);
            asm volatile("cp.async.wait_group 1;\n");
        } else {
            asm volatile("cp.async.wait_group 0;\n");
        }
        __syncthreads();

        const bf16* sA_h = (const bf16*)(sm + cur * PST);
        const bf16* sA_l = (const bf16*)(sm + cur * PST + PT);
        const bf16* sG_h = (const bf16*)(sm + cur * PST + 2 * PT);
        const bf16* sG_l = (const bf16*)(sm + cur * PST + 3 * PT);
        const bf16* sU_h = (const bf16*)(sm + cur * PST + 4 * PT);
        const bf16* sU_l = (const bf16*)(sm + cur * PST + 5 * PT);

#pragma unroll
        for (int kk = 0; kk < BK; kk += 16) {
            uint32_t ah[2][4], al[2][4];
#pragma unroll
            for (int mt = 0; mt < 2; ++mt) {
                int r = wm + mt * 16 + gid;
                ah[mt][0] = *(const uint32_t*)&sA_h[(r    ) * BKPH + kk + 2 * tig];
                ah[mt][1] = *(const uint32_t*)&sA_h[(r + 8) * BKPH + kk + 2 * tig];
                ah[mt][2] = *(const uint32_t*)&sA_h[(r    ) * BKPH + kk + 2 * tig + 8];
                ah[mt][3] = *(const uint32_t*)&sA_h[(r + 8) * BKPH + kk + 2 * tig + 8];
                al[mt][0] = *(const uint32_t*)&sA_l[(r    ) * BKPH + kk + 2 * tig];
                al[mt][1] = *(const uint32_t*)&sA_l[(r + 8) * BKPH + kk + 2 * tig];
                al[mt][2] = *(const uint32_t*)&sA_l[(r    ) * BKPH + kk + 2 * tig + 8];
                al[mt][3] = *(const uint32_t*)&sA_l[(r + 8) * BKPH + kk + 2 * tig + 8];
            }
            {
                uint32_t bh_[4][2], bl_[4][2];
#pragma unroll
                for (int nt = 0; nt < 4; ++nt) {
                    int c = wn + nt * 8 + gid;
                    bh_[nt][0] = *(const uint32_t*)&sG_h[c * BKPH + kk + 2 * tig];
                    bh_[nt][1] = *(const uint32_t*)&sG_h[c * BKPH + kk + 2 * tig + 8];
                    bl_[nt][0] = *(const uint32_t*)&sG_l[c * BKPH + kk + 2 * tig];
                    bl_[nt][1] = *(const uint32_t*)&sG_l[c * BKPH + kk + 2 * tig + 8];
                }
#pragma unroll
                for (int mt = 0; mt < 2; ++mt)
#pragma unroll
                    for (int nt = 0; nt < 4; ++nt) {
                        MMA_BF16(accg[mt][nt], ah[mt][0], ah[mt][1], ah[mt][2], ah[mt][3],
                                 bl_[nt][0], bl_[nt][1]);
                        MMA_BF16(accg[mt][nt], al[mt][0], al[mt][1], al[mt][2], al[mt][3],
                                 bh_[nt][0], bh_[nt][1]);
                        MMA_BF16(accg[mt][nt], ah[mt][0], ah[mt][1], ah[mt][2], ah[mt][3],
                                 bh_[nt][0], bh_[nt][1]);
                    }
            }
            {
                uint32_t bh_[4][2], bl_[4][2];
#pragma unroll
                for (int nt = 0; nt < 4; ++nt) {
                    int c = wn + nt * 8 + gid;
                    bh_[nt][0] = *(const uint32_t*)&sU_h[c * BKPH + kk + 2 * tig];
                    bh_[nt][1] = *(const uint32_t*)&sU_h[c * BKPH + kk + 2 * tig + 8];
                    bl_[nt][0] = *(const uint32_t*)&sU_l[c * BKPH + kk + 2 * tig];
                    bl_[nt][1] = *(const uint32_t*)&sU_l[c * BKPH + kk + 2 * tig + 8];
                }
#pragma unroll
                for (int mt = 0; mt < 2; ++mt)
#pragma unroll
                    for (int nt = 0; nt < 4; ++nt) {
                        MMA_BF16(accu[mt][nt], ah[mt][0], ah[mt][1], ah[mt][2], ah[mt][3],
                                 bl_[nt][0], bl_[nt][1]);
                        MMA_BF16(accu[mt][nt], al[mt][0], al[mt][1], al[mt][2], al[mt][3],
                                 bh_[nt][0], bh_[nt][1]);
                        MMA_BF16(accu[mt][nt], ah[mt][0], ah[mt][1], ah[mt][2], ah[mt][3],
                                 bh_[nt][0], bh_[nt][1]);
                    }
            }
        }
        __syncthreads();
    }

#pragma unroll
    for (int mt = 0; mt < 2; ++mt) {
#pragma unroll
        for (int nt = 0; nt < 4; ++nt) {
            int r0 = m0 + wm + mt * 16 + gid;
            int c  = n0 + wn + nt * 8 + tig * 2;
#pragma unroll
            for (int half = 0; half < 2; ++half) {
                int rr = r0 + half * 8;
                float gv0 = accg[mt][nt][2 * half],     uv0 = accu[mt][nt][2 * half];
                float gv1 = accg[mt][nt][2 * half + 1], uv1 = accu[mt][nt][2 * half + 1];
                float a0 = gv0 * sigmoidf_(gv0) * uv0;
                float a1 = gv1 * sigmoidf_(gv1) * uv1;
                bf16 h0, l0, h1, l1;
                split_bf16(a0, h0, l0);
                split_bf16(a1, h1, l1);
                size_t o = (size_t)rr * Nfull + c;
                *reinterpret_cast<bf162*>(out_hi + o) = __halves2bfloat162(h0, h1);
                *reinterpret_cast<bf162*>(out_lo + o) = __halves2bfloat162(l0, l1);
            }
        }
    }
}

// ---------------------------------------------------------------------------
// RMSNorm with optional split-K partial reduction (H=512, block=128).
// haspart: x = xin + p0 + p1 (written back to xout = residual stream).
// split!=0: write bf16 hi/lo; else fp32 out (final norm -> d_out).
// ---------------------------------------------------------------------------
__global__ __launch_bounds__(128) void rmsnorm_kernel(
    const float* __restrict__ xin, const float* __restrict__ p0,
    const float* __restrict__ p1, const float* __restrict__ w,
    float* __restrict__ xout, float* __restrict__ out,
    bf16* __restrict__ out_hi, bf16* __restrict__ out_lo,
    int haspart, int split)
{
    const int row = blockIdx.x, tid = threadIdx.x;
    float4 v = reinterpret_cast<const float4*>(xin + (size_t)row * HDIM)[tid];
    if (haspart) {
        float4 a = reinterpret_cast<const float4*>(p0 + (size_t)row * HDIM)[tid];
        float4 b = reinterpret_cast<const float4*>(p1 + (size_t)row * HDIM)[tid];
        v.x += a.x + b.x; v.y += a.y + b.y;
        v.z += a.z + b.z; v.w += a.w + b.w;
        reinterpret_cast<float4*>(xout + (size_t)row * HDIM)[tid] = v;
    }
    float ss = v.x * v.x + v.y * v.y + v.z * v.z + v.w * v.w;
#pragma unroll
    for (int o = 16; o; o >>= 1) ss += __shfl_xor_sync(0xffffffffu, ss, o);
    __shared__ float sred[4];
    if ((tid & 31) == 0) sred[tid >> 5] = ss;
    __syncthreads();
    float tot = sred[0] + sred[1] + sred[2] + sred[3];
    float inv = rsqrtf(tot * (1.0f / (float)HDIM) + EPSV);
    float4 wv = reinterpret_cast<const float4*>(w)[tid];
    float4 o4 = make_float4(v.x * inv * wv.x, v.y * inv * wv.y,
                            v.z * inv * wv.z, v.w * inv * wv.w);
    if (split) {
        bf16 hx, lx, hy, ly, hz, lz, hw, lw;
        split_bf16(o4.x, hx, lx); split_bf16(o4.y, hy, ly);
        split_bf16(o4.z, hz, lz); split_bf16(o4.w, hw, lw);
        bf162* oh = reinterpret_cast<bf162*>(out_hi + (size_t)row * HDIM);
        bf162* ol = reinterpret_cast<bf162*>(out_lo + (size_t)row * HDIM);
        oh[tid * 2]     = __halves2bfloat162(hx, hy);
        oh[tid * 2 + 1] = __halves2bfloat162(hz, hw);
        ol[tid * 2]     = __halves2bfloat162(lx, ly);
        ol[tid * 2 + 1] = __halves2bfloat162(lz, lw);
    } else {
        reinterpret_cast<float4*>(out + (size_t)row * HDIM)[tid] = o4;
    }
}

// ---------------------------------------------------------------------------
// mLSTM step (zero state) + per-head RMSNorm + output gate.
// ---------------------------------------------------------------------------
__global__ __launch_bounds__(256) void mlstm_kernel(
    const float* __restrict__ q, const float* __restrict__ k,
    const float* __restrict__ v, const float* __restrict__ ogp,
    const float* __restrict__ ifp,
    const float* __restrict__ bi, const float* __restrict__ bf,
    const float* __restrict__ mhw,
    bf16* __restrict__ hv_hi, bf16* __restrict__ hv_lo)
{
    const int t = blockIdx.x;
    const int h = threadIdx.x >> 5;
    const int lane = threadIdx.x & 31;

    float ip = softcapf(ifp[(size_t)t * 64 + h]      + bi[h]);
    float fp = softcapf(ifp[(size_t)t * 64 + 8 + h]  + bf[h]);
    float flog = logsigf(fp);
    float m = fmaxf(flog, ip);
    float iact = expf(ip - m);

    float qd = q[(size_t)t * QKDIM + h * DHQK + lane];
    float kd = k[(size_t)t * QKDIM + h * DHQK + lane];
    float s = qd * kd;
#pragma unroll
    for (int o = 16; o; o >>= 1) s += __shfl_xor_sync(0xffffffffu, s, o);
    s *= 0.17677669529663687f;  // 32^-0.5

    float qn = iact * s;
    float denom = fmaxf(fabsf(qn), expf(-m)) + EPSV;
    float c = iact * s / denom;

    const int base = t * VDIM + h * DHV;
    float v0 = v[base + lane], v1 = v[base + 32 + lane];
    float h0 = c * v0, h1 = c * v1;

    float ms = h0 * h0 + h1 * h1;
#pragma unroll
    for (int o = 16; o; o >>= 1) ms += __shfl_xor_sync(0xffffffffu, ms, o);
    float inv = rsqrtf(ms * (1.0f / (float)DHV) + EPSV);

    float w0 = mhw[h * DHV + lane],      w1 = mhw[h * DHV + 32 + lane];
    float g0 = sigmoidf_(ogp[base + lane]);
    float g1 = sigmoidf_(ogp[base + 32 + lane]);
    float r0 = h0 * inv * w0 * g0;
    float r1 = h1 * inv * w1 * g1;
    bf16 rh, rl;
    split_bf16(r0, rh, rl);
    hv_hi[base + lane] = rh;           hv_lo[base + lane] = rl;
    split_bf16(r1, rh, rl);
    hv_hi[base + 32 + lane] = rh;      hv_lo[base + 32 + lane] = rl;
}

// ---------------------------------------------------------------------------
// Host launcher
// ---------------------------------------------------------------------------
static inline void* sym_addr_v(const void* sym) {
    void* p = nullptr;
    cudaGetSymbolAddress(&p, sym);
    return p;
}
#define SYMF(s)  ((float*)sym_addr_v(s))
#define SYMB(s)  ((bf16*)sym_addr_v(s))

static inline void gemm_multi(const bf16* Ahi, const bf16* Alo,
                              int M, int K, const GemmDesc& d) {
    int nb = d.seg[d.nseg - 1].nstart + d.seg[d.nseg - 1].N / BN;
    dim3 grid(nb, M / BM);
    gemm_bf16x3_kernel<<<grid, 128>>>(Ahi, Alo, M, K, d);
}

extern "C" void kernel_launch(void* const* d_in, const int* in_sizes, int n_in,
                              void* d_out, int out_size)
{
    (void)in_sizes; (void)n_in; (void)out_size;
    const float* u       = (const float*)d_in[0];
    const float* norm1_w = (const float*)d_in[1];
    const float* Wq      = (const float*)d_in[2];
    const float* Wk      = (const float*)d_in[3];
    const float* Wv      = (const float*)d_in[4];
    const float* Wi      = (const float*)d_in[5];
    const float* bi      = (const float*)d_in[6];
    const float* Wf      = (const float*)d_in[7];
    const float* bf_     = (const float*)d_in[8];
    const float* mh_w    = (const float*)d_in[9];
    const float* Wog     = (const float*)d_in[10];
    const float* Wout    = (const float*)d_in[11];
    const float* norm2_w = (const float*)d_in[12];
    const float* W_up    = (const float*)d_in[13];
    const float* W_gate  = (const float*)d_in[14];
    const float* W_down  = (const float*)d_in[15];
    const float* final_w = (const float*)d_in[16];
    float* out = (float*)d_out;

    cudaFuncSetAttribute(gemm_paired_kernel,
                         cudaFuncAttributeMaxDynamicSharedMemorySize, 2 * PST);

    float* x   = SYMF(g_x);
    float* qb  = SYMF(g_q);
    float* kb  = SYMF(g_k);
    float* vb  = SYMF(g_v);
    float* ogb = SYMF(g_og);
    float* ifb = SYMF(g_if);
    float* p0  = SYMF(g_p0);
    float* p1  = SYMF(g_p1);
    bf16* xnh  = SYMB(g_xn_h),  *xnl  = SYMB(g_xn_l);
    bf16* hvh  = SYMB(g_hv_h),  *hvl  = SYMB(g_hv_l);
    bf16* acth = SYMB(g_act_h), *actl = SYMB(g_act_l);

    bf16* wqh = SYMB(w_q_h),  *wql = SYMB(w_q_l);
    bf16* wkh = SYMB(w_k_h),  *wkl = SYMB(w_k_l);
    bf16* wvh = SYMB(w_v_h),  *wvl = SYMB(w_v_l);
    bf16* wogh= SYMB(w_og_h), *wogl= SYMB(w_og_l);
    bf16* woh = SYMB(w_o_h),  *wol = SYMB(w_o_l);
    bf16* wgh = SYMB(w_g_h),  *wgl = SYMB(w_g_l);
    bf16* wuh = SYMB(w_u_h),  *wul = SYMB(w_u_l);
    bf16* wdh = SYMB(w_d_h),  *wdl = SYMB(w_d_l);
    bf16* wifh= SYMB(w_if_h), *wifl= SYMB(w_if_l);

    copy_kernel<<<(NTOK * HDIM / 4 + 255) / 256, 256>>>(u, x, NTOK * HDIM / 4);

    {
        SplitDesc sd;
        sd.nseg = 3;
        sd.seg[0] = { W_gate, wgh, wgl, HDIM, FDIM, 0    };
        sd.seg[1] = { W_up,   wuh, wul, HDIM, FDIM, 704  };
        sd.seg[2] = { W_down, wdh, wdl, FDIM, HDIM, 1408 };
        dim3 grid(2112, 1, LAYERS);
        split_transpose_multi_kernel<<<grid, dim3(32, 8)>>>(sd);
    }
    {
        SplitDesc sd;
        sd.nseg = 5;
        sd.seg[0] = { Wq,   wqh,  wql,  HDIM, QKDIM, 0   };
        sd.seg[1] = { Wk,   wkh,  wkl,  HDIM, QKDIM, 128 };
        sd.seg[2] = { Wv,   wvh,  wvl,  HDIM, VDIM,  256 };
        sd.seg[3] = { Wog,  wogh, wogl, HDIM, VDIM,  512 };
        sd.seg[4] = { Wout, woh,  wol,  VDIM, HDIM,  768 };
        dim3 grid(1024, 1, LAYERS);
        split_transpose_multi_kernel<<<grid, dim3(32, 8)>>>(sd);
    }
    pack_wif_kernel<<<LAYERS * 64, 128>>>(Wi, Wf, wifh, wifl);

    // d4 partials of previous FFN block pending? (layer 0: none)
    int pending_d4 = 0;

    for (int l = 0; l < LAYERS; ++l) {
        const size_t oqk = (size_t)l * QKDIM * HDIM;
        const size_t ov  = (size_t)l * VDIM * HDIM;
        const size_t of  = (size_t)l * FDIM * HDIM;
        const size_t oif = (size_t)l * 64 * HDIM;

        // --- mLSTM block ---
        // rmsnorm1 (reduces previous layer's d4 partials if present)
        rmsnorm_kernel<<<NTOK, 128>>>(x, p0, p1, norm1_w + l * HDIM,
                                      x, nullptr, xnh, xnl, pending_d4, 1);

        GemmDesc d1;            // q | k | v | og | if
        d1.nseg = 5;
        d1.seg[0] = { wqh + oqk,  wql + oqk,  qb,  nullptr, QKDIM, 0,  0, HDIM };
        d1.seg[1] = { wkh + oqk,  wkl + oqk,  kb,  nullptr, QKDIM, 4,  0, HDIM };
        d1.seg[2] = { wvh + ov,   wvl + ov,   vb,  nullptr, VDIM,  8,  0, HDIM };
        d1.seg[3] = { wogh + ov,  wogl + ov,  ogb, nullptr, VDIM,  16, 0, HDIM };
        d1.seg[4] = { wifh + oif, wifl + oif, ifb, nullptr, 64,    24, 0, HDIM };
        gemm_multi(xnh, xnl, NTOK, HDIM, d1);

        mlstm_kernel<<<NTOK, 256>>>(qb, kb, vb, ogb, ifb,
                                    bi + l * NHEAD, bf_ + l * NHEAD,
                                    mh_w + (size_t)l * NHEAD * DHV, hvh, hvl);

        GemmDesc d2;            // hv @ Wout -> p0,p1 (split-K=2)
        d2.nseg = 2;
        d2.seg[0] = { woh + ov, wol + ov, p0, nullptr, HDIM, 0, 0,   256 };
        d2.seg[1] = { woh + ov, wol + ov, p1, nullptr, HDIM, 8, 256, 256 };
        gemm_multi(hvh, hvl, NTOK, VDIM, d2);

        // --- FFN block ---
        // rmsnorm2 reduces d2 partials: x += p0 + p1
        rmsnorm_kernel<<<NTOK, 128>>>(x, p0, p1, norm2_w + l * HDIM,
                                      x, nullptr, xnh, xnl, 1, 1);

        {
            dim3 grid(FDIM / BN, NTOK / BM);
            gemm_paired_kernel<<<grid, 128, 2 * PST>>>(
                xnh, xnl, wgh + of, wgl + of, wuh + of, wul + of,
                acth, actl, NTOK, HDIM, FDIM);
        }

        GemmDesc d4;            // act @ W_down -> p0,p1 (split-K=2)
        d4.nseg = 2;
        d4.seg[0] = { wdh + (size_t)l * HDIM * FDIM,
                      wdl + (size_t)l * HDIM * FDIM, p0, nullptr, HDIM, 0, 0,   704 };
        d4.seg[1] = { wdh + (size_t)l * HDIM * FDIM,
                      wdl + (size_t)l * HDIM * FDIM, p1, nullptr, HDIM, 8, 704, 704 };
        gemm_multi(acth, actl, NTOK, FDIM, d4);
        pending_d4 = 1;
    }

    // final rmsnorm reduces layer-3 d4 partials, writes fp32 d_out
    rmsnorm_kernel<<<NTOK, 128>>>(x, p0, p1, final_w,
                                  x, out, nullptr, nullptr, 1, 0);
}

// round 17
// speedup vs baseline: 1.2108x; 1.0192x over previous
#include <cuda_runtime.h>
#include <cuda_bf16.h>
#include <cstdint>

// ---------------------------------------------------------------------------
// Problem constants
// ---------------------------------------------------------------------------
#define LAYERS 4
#define HDIM   512
#define NHEAD  8
#define DHQK   32
#define DHV    64
#define QKDIM  (NHEAD * DHQK)   // 256
#define VDIM   (NHEAD * DHV)    // 512
#define FDIM   1408
#define NTOK   2048              // B*P = 8*256
#define CAPV   15.0f
#define EPSV   1e-6f

typedef __nv_bfloat16  bf16;
typedef __nv_bfloat162 bf162;

// ---------------------------------------------------------------------------
// Device scratch (static: no allocation allowed)
// ---------------------------------------------------------------------------
__device__ float g_x   [NTOK * HDIM];
__device__ float g_q   [NTOK * QKDIM];
__device__ float g_k   [NTOK * QKDIM];
__device__ float g_v   [NTOK * VDIM];
__device__ float g_og  [NTOK * VDIM];
__device__ float g_if  [NTOK * 64];
__device__ float g_p0  [NTOK * HDIM];   // split-K partials
__device__ float g_p1  [NTOK * HDIM];
__device__ float g_p2  [NTOK * HDIM];
__device__ float g_p3  [NTOK * HDIM];

// bf16 hi/lo split activations (GEMM A-operands, [M][K])
__device__ bf16 g_xn_h [NTOK * HDIM];
__device__ bf16 g_xn_l [NTOK * HDIM];
__device__ bf16 g_hv_h [NTOK * VDIM];
__device__ bf16 g_hv_l [NTOK * VDIM];
__device__ bf16 g_act_h[NTOK * FDIM];
__device__ bf16 g_act_l[NTOK * FDIM];

// bf16 hi/lo split weights, TRANSPOSED to [N][K] (GEMM B-operands)
__device__ bf16 w_q_h [LAYERS * QKDIM * HDIM];
__device__ bf16 w_q_l [LAYERS * QKDIM * HDIM];
__device__ bf16 w_k_h [LAYERS * QKDIM * HDIM];
__device__ bf16 w_k_l [LAYERS * QKDIM * HDIM];
__device__ bf16 w_v_h [LAYERS * VDIM * HDIM];
__device__ bf16 w_v_l [LAYERS * VDIM * HDIM];
__device__ bf16 w_og_h[LAYERS * VDIM * HDIM];
__device__ bf16 w_og_l[LAYERS * VDIM * HDIM];
__device__ bf16 w_o_h [LAYERS * HDIM * VDIM];
__device__ bf16 w_o_l [LAYERS * HDIM * VDIM];
__device__ bf16 w_g_h [LAYERS * FDIM * HDIM];
__device__ bf16 w_g_l [LAYERS * FDIM * HDIM];
__device__ bf16 w_u_h [LAYERS * FDIM * HDIM];
__device__ bf16 w_u_l [LAYERS * FDIM * HDIM];
__device__ bf16 w_d_h [LAYERS * HDIM * FDIM];
__device__ bf16 w_d_l [LAYERS * HDIM * FDIM];
__device__ bf16 w_if_h[LAYERS * 64 * HDIM];
__device__ bf16 w_if_l[LAYERS * 64 * HDIM];

// ---------------------------------------------------------------------------
// Helpers
// ---------------------------------------------------------------------------
__device__ __forceinline__ float softcapf(float x) {
    return CAPV * tanhf(x * (1.0f / CAPV));
}
__device__ __forceinline__ float logsigf(float x) {
    return (x >= 0.0f) ? -log1pf(expf(-x)) : (x - log1pf(expf(x)));
}
__device__ __forceinline__ float sigmoidf_(float x) {
    return 1.0f / (1.0f + expf(-x));
}
__device__ __forceinline__ void cpasync16(uint32_t dst, const void* src) {
    asm volatile("cp.async.cg.shared.global [%0], [%1], 16;\n"
                 :: "r"(dst), "l"(src));
}
__device__ __forceinline__ void split_bf16(float v, bf16& h, bf16& l) {
    h = __float2bfloat16_rn(v);
    l = __float2bfloat16_rn(v - __bfloat162float(h));
}

#define MMA_BF16(acc, a0, a1, a2, a3, b0, b1)                                  \
    asm volatile(                                                              \
        "mma.sync.aligned.m16n8k16.row.col.f32.bf16.bf16.f32 "                 \
        "{%0,%1,%2,%3}, {%4,%5,%6,%7}, {%8,%9}, {%0,%1,%2,%3};\n"              \
        : "+f"(acc[0]), "+f"(acc[1]), "+f"(acc[2]), "+f"(acc[3])               \
        : "r"(a0), "r"(a1), "r"(a2), "r"(a3), "r"(b0), "r"(b1))

// ---------------------------------------------------------------------------
// Plain device copy
// ---------------------------------------------------------------------------
__global__ __launch_bounds__(256) void copy_kernel(
    const float* __restrict__ in, float* __restrict__ out, int n4)
{
    int i = blockIdx.x * blockDim.x + threadIdx.x;
    if (i < n4) reinterpret_cast<float4*>(out)[i] =
        reinterpret_cast<const float4*>(in)[i];
}

// ---------------------------------------------------------------------------
// Multi-segment weight transform: fp32 W[K][N] -> bf16 hi/lo transposed [N][K].
// ---------------------------------------------------------------------------
#define MAXWSEG 5
struct SplitSeg {
    const float* in;
    bf16* hi;
    bf16* lo;
    int K, N;
    int tstart;
};
struct SplitDesc {
    int nseg;
    SplitSeg seg[MAXWSEG];
};

__global__ __launch_bounds__(256) void split_transpose_multi_kernel(SplitDesc d)
{
    __shared__ float t[32][33];
    const int tile = blockIdx.x;
    int si = 0;
#pragma unroll
    for (int s = 1; s < MAXWSEG; ++s)
        if (s < d.nseg && tile >= d.seg[s].tstart) si = s;
    const SplitSeg& sg = d.seg[si];
    const int l = blockIdx.z;
    const float* in = sg.in + (size_t)l * sg.K * sg.N;
    bf16* hi = sg.hi + (size_t)l * sg.N * sg.K;
    bf16* lo = sg.lo + (size_t)l * sg.N * sg.K;

    const int tl   = tile - sg.tstart;
    const int ntn  = sg.N / 32;
    const int n0   = (tl % ntn) * 32;
    const int k0   = (tl / ntn) * 32;
    const int tx = threadIdx.x, ty = threadIdx.y;
#pragma unroll
    for (int j = 0; j < 4; ++j)
        t[ty + 8 * j][tx] = in[(size_t)(k0 + ty + 8 * j) * sg.N + n0 + tx];
    __syncthreads();
#pragma unroll
    for (int j = 0; j < 4; ++j) {
        float v = t[tx][ty + 8 * j];
        bf16 h, lv; split_bf16(v, h, lv);
        size_t o = (size_t)(n0 + ty + 8 * j) * sg.K + k0 + tx;
        hi[o] = h; lo[o] = lv;
    }
}

// ---------------------------------------------------------------------------
// Pack [Wi | Wf | zeros] -> transposed split [64][HDIM] per layer.
// ---------------------------------------------------------------------------
__global__ void pack_wif_kernel(const float* __restrict__ Wi,
                                const float* __restrict__ Wf,
                                bf16* __restrict__ hi, bf16* __restrict__ lo)
{
    const int l = blockIdx.x >> 6;
    const int n = blockIdx.x & 63;
    for (int k = threadIdx.x; k < HDIM; k += blockDim.x) {
        float val = 0.0f;
        if (n < NHEAD)          val = Wi[((size_t)l * HDIM + k) * NHEAD + n];
        else if (n < 2 * NHEAD) val = Wf[((size_t)l * HDIM + k) * NHEAD + (n - NHEAD)];
        bf16 h, lv; split_bf16(val, h, lv);
        size_t o = ((size_t)l * 64 + n) * HDIM + k;
        hi[o] = h; lo[o] = lv;
    }
}

// ---------------------------------------------------------------------------
// Multi-segment bf16x3 GEMM with per-segment K-range (split-K support).
// C_s[M,N_s] = A[M, koff:koff+ksz] @ W_s[koff:koff+ksz, N_s] (+ Res_s)
// acc += ah*bl + al*bh + ah*bh  (fp32 accumulate)
// CTA 64x64x32, 128 threads (4 warps 2x2, warp 32x32), 2-stage cp.async.
// ---------------------------------------------------------------------------
#define MAXSEG 5
struct GemmSeg {
    const bf16*  Bh;
    const bf16*  Bl;
    float*       C;
    const float* Res;   // nullptr = no residual add
    int          N;
    int          nstart;
    int          koff;  // K-range start
    int          ksz;   // K-range size (multiple of BK)
};
struct GemmDesc {
    int nseg;
    GemmSeg seg[MAXSEG];
};

#define BM 64
#define BN 64
#define BK 32
#define BKPH 40   // 80B rows: banks (20r)%32 distinct -> conflict-free

__global__ __launch_bounds__(128) void gemm_bf16x3_kernel(
    const bf16* __restrict__ Ahi, const bf16* __restrict__ Alo,
    int M, int K, GemmDesc d)
{
    __shared__ bf16 Ah[2][BM][BKPH];
    __shared__ bf16 Al[2][BM][BKPH];
    __shared__ bf16 Bh[2][BN][BKPH];   // [n][k]
    __shared__ bf16 Bl[2][BN][BKPH];

    const int nblk = blockIdx.x;
    int si = 0;
#pragma unroll
    for (int t = 1; t < MAXSEG; ++t)
        if (t < d.nseg && nblk >= d.seg[t].nstart) si = t;
    const bf16* __restrict__ SBh = d.seg[si].Bh;
    const bf16* __restrict__ SBl = d.seg[si].Bl;
    float*      __restrict__ C   = d.seg[si].C;
    const float* __restrict__ Res = d.seg[si].Res;
    const int N   = d.seg[si].N;
    const int n0  = (nblk - d.seg[si].nstart) * BN;
    const int kof = d.seg[si].koff;
    const int nk  = d.seg[si].ksz / BK;
    const int m0  = blockIdx.y * BM;

    const int tid  = threadIdx.x;
    const int warp = tid >> 5;
    const int lane = tid & 31;
    const int wm   = (warp >> 1) * 32;
    const int wn   = (warp & 1) * 32;
    const int gid  = lane >> 2;
    const int tig  = lane & 3;

    int rrow[2], rc16[2];
    uint32_t ah_dst[2][2], al_dst[2][2], bh_dst[2][2], bl_dst[2][2];
#pragma unroll
    for (int it = 0; it < 2; ++it) {
        int idx = tid + it * 128;
        rrow[it] = idx >> 2;
        rc16[it] = idx & 3;
#pragma unroll
        for (int s = 0; s < 2; ++s) {
            ah_dst[s][it] = (uint32_t)__cvta_generic_to_shared(&Ah[s][rrow[it]][rc16[it] * 8]);
            al_dst[s][it] = (uint32_t)__cvta_generic_to_shared(&Al[s][rrow[it]][rc16[it] * 8]);
            bh_dst[s][it] = (uint32_t)__cvta_generic_to_shared(&Bh[s][rrow[it]][rc16[it] * 8]);
            bl_dst[s][it] = (uint32_t)__cvta_generic_to_shared(&Bl[s][rrow[it]][rc16[it] * 8]);
        }
    }

    float acc[2][4][4];
#pragma unroll
    for (int mt = 0; mt < 2; ++mt)
#pragma unroll
        for (int nt = 0; nt < 4; ++nt)
#pragma unroll
            for (int r = 0; r < 4; ++r) acc[mt][nt][r] = 0.0f;

#pragma unroll
    for (int it = 0; it < 2; ++it) {
        cpasync16(ah_dst[0][it], Ahi + (size_t)(m0 + rrow[it]) * K + kof + rc16[it] * 8);
        cpasync16(al_dst[0][it], Alo + (size_t)(m0 + rrow[it]) * K + kof + rc16[it] * 8);
        cpasync16(bh_dst[0][it], SBh + (size_t)(n0 + rrow[it]) * K + kof + rc16[it] * 8);
        cpasync16(bl_dst[0][it], SBl + (size_t)(n0 + rrow[it]) * K + kof + rc16[it] * 8);
    }
    asm volatile("cp.async.commit_group;\n");

    for (int kt = 0; kt < nk; ++kt) {
        const int cur = kt & 1;
        if (kt + 1 < nk) {
            const int nxt = cur ^ 1;
            const int koff = kof + (kt + 1) * BK;
#pragma unroll
            for (int it = 0; it < 2; ++it) {
                cpasync16(ah_dst[nxt][it], Ahi + (size_t)(m0 + rrow[it]) * K + koff + rc16[it] * 8);
                cpasync16(al_dst[nxt][it], Alo + (size_t)(m0 + rrow[it]) * K + koff + rc16[it] * 8);
                cpasync16(bh_dst[nxt][it], SBh + (size_t)(n0 + rrow[it]) * K + koff + rc16[it] * 8);
                cpasync16(bl_dst[nxt][it], SBl + (size_t)(n0 + rrow[it]) * K + koff + rc16[it] * 8);
            }
            asm volatile("cp.async.commit_group;\n");
            asm volatile("cp.async.wait_group 1;\n");
        } else {
            asm volatile("cp.async.wait_group 0;\n");
        }
        __syncthreads();

#pragma unroll
        for (int kk = 0; kk < BK; kk += 16) {
            uint32_t ah[2][4], al[2][4], bh_[4][2], bl_[4][2];
#pragma unroll
            for (int mt = 0; mt < 2; ++mt) {
                int r = wm + mt * 16 + gid;
                ah[mt][0] = *(const uint32_t*)&Ah[cur][r    ][kk + 2 * tig];
                ah[mt][1] = *(const uint32_t*)&Ah[cur][r + 8][kk + 2 * tig];
                ah[mt][2] = *(const uint32_t*)&Ah[cur][r    ][kk + 2 * tig + 8];
                ah[mt][3] = *(const uint32_t*)&Ah[cur][r + 8][kk + 2 * tig + 8];
                al[mt][0] = *(const uint32_t*)&Al[cur][r    ][kk + 2 * tig];
                al[mt][1] = *(const uint32_t*)&Al[cur][r + 8][kk + 2 * tig];
                al[mt][2] = *(const uint32_t*)&Al[cur][r    ][kk + 2 * tig + 8];
                al[mt][3] = *(const uint32_t*)&Al[cur][r + 8][kk + 2 * tig + 8];
            }
#pragma unroll
            for (int nt = 0; nt < 4; ++nt) {
                int c = wn + nt * 8 + gid;
                bh_[nt][0] = *(const uint32_t*)&Bh[cur][c][kk + 2 * tig];
                bh_[nt][1] = *(const uint32_t*)&Bh[cur][c][kk + 2 * tig + 8];
                bl_[nt][0] = *(const uint32_t*)&Bl[cur][c][kk + 2 * tig];
                bl_[nt][1] = *(const uint32_t*)&Bl[cur][c][kk + 2 * tig + 8];
            }
#pragma unroll
            for (int mt = 0; mt < 2; ++mt)
#pragma unroll
                for (int nt = 0; nt < 4; ++nt) {
                    MMA_BF16(acc[mt][nt], ah[mt][0], ah[mt][1], ah[mt][2], ah[mt][3],
                             bl_[nt][0], bl_[nt][1]);
                    MMA_BF16(acc[mt][nt], al[mt][0], al[mt][1], al[mt][2], al[mt][3],
                             bh_[nt][0], bh_[nt][1]);
                    MMA_BF16(acc[mt][nt], ah[mt][0], ah[mt][1], ah[mt][2], ah[mt][3],
                             bh_[nt][0], bh_[nt][1]);
                }
        }
        __syncthreads();
    }

#pragma unroll
    for (int mt = 0; mt < 2; ++mt) {
#pragma unroll
        for (int nt = 0; nt < 4; ++nt) {
            int r0 = m0 + wm + mt * 16 + gid;
            int c  = n0 + wn + nt * 8 + tig * 2;
            float2 v0 = make_float2(acc[mt][nt][0], acc[mt][nt][1]);
            float2 v1 = make_float2(acc[mt][nt][2], acc[mt][nt][3]);
            if (Res != nullptr) {
                float2 r = *reinterpret_cast<const float2*>(Res + (size_t)r0 * N + c);
                v0.x += r.x; v0.y += r.y;
                r = *reinterpret_cast<const float2*>(Res + (size_t)(r0 + 8) * N + c);
                v1.x += r.x; v1.y += r.y;
            }
            *reinterpret_cast<float2*>(C + (size_t)r0 * N + c)       = v0;
            *reinterpret_cast<float2*>(C + (size_t)(r0 + 8) * N + c) = v1;
        }
    }
}

// ---------------------------------------------------------------------------
// Paired gate|up GEMM + fused SwiGLU epilogue.
// ---------------------------------------------------------------------------
#define PST 30720
#define PT  5120

__global__ __launch_bounds__(128) void gemm_paired_kernel(
    const bf16* __restrict__ Ahi, const bf16* __restrict__ Alo,
    const bf16* __restrict__ Bgh, const bf16* __restrict__ Bgl,
    const bf16* __restrict__ Buh, const bf16* __restrict__ Bul,
    bf16* __restrict__ out_hi, bf16* __restrict__ out_lo,
    int M, int K, int Nfull)
{
    extern __shared__ __align__(16) char sm[];
    const uint32_t smb = (uint32_t)__cvta_generic_to_shared(sm);

    const int n0 = blockIdx.x * BN;
    const int m0 = blockIdx.y * BM;

    const int tid  = threadIdx.x;
    const int warp = tid >> 5;
    const int lane = tid & 31;
    const int wm   = (warp >> 1) * 32;
    const int wn   = (warp & 1) * 32;
    const int gid  = lane >> 2;
    const int tig  = lane & 3;

    int rrow[2], rc16[2];
#pragma unroll
    for (int it = 0; it < 2; ++it) {
        int idx = tid + it * 128;
        rrow[it] = idx >> 2;
        rc16[it] = idx & 3;
    }

    float accg[2][4][4], accu[2][4][4];
#pragma unroll
    for (int mt = 0; mt < 2; ++mt)
#pragma unroll
        for (int nt = 0; nt < 4; ++nt)
#pragma unroll
            for (int r = 0; r < 4; ++r) { accg[mt][nt][r] = 0.0f; accu[mt][nt][r] = 0.0f; }

    const int nk = K / BK;

    auto load_stage = [&](int s, int koff) {
        const uint32_t sb = smb + s * PST;
#pragma unroll
        for (int it = 0; it < 2; ++it) {
            const uint32_t doff = (uint32_t)(rrow[it] * 80 + rc16[it] * 16);
            const size_t asrc = (size_t)(m0 + rrow[it]) * K + koff + rc16[it] * 8;
            const size_t bsrc = (size_t)(n0 + rrow[it]) * K + koff + rc16[it] * 8;
            cpasync16(sb + doff,            Ahi + asrc);
            cpasync16(sb + PT     + doff,   Alo + asrc);
            cpasync16(sb + 2 * PT + doff,   Bgh + bsrc);
            cpasync16(sb + 3 * PT + doff,   Bgl + bsrc);
            cpasync16(sb + 4 * PT + doff,   Buh + bsrc);
            cpasync16(sb + 5 * PT + doff,   Bul + bsrc);
        }
        asm volatile("cp.async.commit_group;\n");
    };

    load_stage(0, 0);

    for (int kt = 0; kt < nk; ++kt) {
        const int cur = kt & 1;
        if (kt + 1 < nk) {
            load_stage(cur ^ 1, (kt + 1) * BK);
            asm volatile("cp.async.wait_group 1;\n");
        } else {
            asm volatile("cp.async.wait_group 0;\n");
        }
        __syncthreads();

        const bf16* sA_h = (const bf16*)(sm + cur * PST);
        const bf16* sA_l = (const bf16*)(sm + cur * PST + PT);
        const bf16* sG_h = (const bf16*)(sm + cur * PST + 2 * PT);
        const bf16* sG_l = (const bf16*)(sm + cur * PST + 3 * PT);
        const bf16* sU_h = (const bf16*)(sm + cur * PST + 4 * PT);
        const bf16* sU_l = (const bf16*)(sm + cur * PST + 5 * PT);

#pragma unroll
        for (int kk = 0; kk < BK; kk += 16) {
            uint32_t ah[2][4], al[2][4];
#pragma unroll
            for (int mt = 0; mt < 2; ++mt) {
                int r = wm + mt * 16 + gid;
                ah[mt][0] = *(const uint32_t*)&sA_h[(r    ) * BKPH + kk + 2 * tig];
                ah[mt][1] = *(const uint32_t*)&sA_h[(r + 8) * BKPH + kk + 2 * tig];
                ah[mt][2] = *(const uint32_t*)&sA_h[(r    ) * BKPH + kk + 2 * tig + 8];
                ah[mt][3] = *(const uint32_t*)&sA_h[(r + 8) * BKPH + kk + 2 * tig + 8];
                al[mt][0] = *(const uint32_t*)&sA_l[(r    ) * BKPH + kk + 2 * tig];
                al[mt][1] = *(const uint32_t*)&sA_l[(r + 8) * BKPH + kk + 2 * tig];
                al[mt][2] = *(const uint32_t*)&sA_l[(r    ) * BKPH + kk + 2 * tig + 8];
                al[mt][3] = *(const uint32_t*)&sA_l[(r + 8) * BKPH + kk + 2 * tig + 8];
            }
            {
                uint32_t bh_[4][2], bl_[4][2];
#pragma unroll
                for (int nt = 0; nt < 4; ++nt) {
                    int c = wn + nt * 8 + gid;
                    bh_[nt][0] = *(const uint32_t*)&sG_h[c * BKPH + kk + 2 * tig];
                    bh_[nt][1] = *(const uint32_t*)&sG_h[c * BKPH + kk + 2 * tig + 8];
                    bl_[nt][0] = *(const uint32_t*)&sG_l[c * BKPH + kk + 2 * tig];
                    bl_[nt][1] = *(const uint32_t*)&sG_l[c * BKPH + kk + 2 * tig + 8];
                }
#pragma unroll
                for (int mt = 0; mt < 2; ++mt)
#pragma unroll
                    for (int nt = 0; nt < 4; ++nt) {
                        MMA_BF16(accg[mt][nt], ah[mt][0], ah[mt][1], ah[mt][2], ah[mt][3],
                                 bl_[nt][0], bl_[nt][1]);
                        MMA_BF16(accg[mt][nt], al[mt][0], al[mt][1], al[mt][2], al[mt][3],
                                 bh_[nt][0], bh_[nt][1]);
                        MMA_BF16(accg[mt][nt], ah[mt][0], ah[mt][1], ah[mt][2], ah[mt][3],
                                 bh_[nt][0], bh_[nt][1]);
                    }
            }
            {
                uint32_t bh_[4][2], bl_[4][2];
#pragma unroll
                for (int nt = 0; nt < 4; ++nt) {
                    int c = wn + nt * 8 + gid;
                    bh_[nt][0] = *(const uint32_t*)&sU_h[c * BKPH + kk + 2 * tig];
                    bh_[nt][1] = *(const uint32_t*)&sU_h[c * BKPH + kk + 2 * tig + 8];
                    bl_[nt][0] = *(const uint32_t*)&sU_l[c * BKPH + kk + 2 * tig];
                    bl_[nt][1] = *(const uint32_t*)&sU_l[c * BKPH + kk + 2 * tig + 8];
                }
#pragma unroll
                for (int mt = 0; mt < 2; ++mt)
#pragma unroll
                    for (int nt = 0; nt < 4; ++nt) {
                        MMA_BF16(accu[mt][nt], ah[mt][0], ah[mt][1], ah[mt][2], ah[mt][3],
                                 bl_[nt][0], bl_[nt][1]);
                        MMA_BF16(accu[mt][nt], al[mt][0], al[mt][1], al[mt][2], al[mt][3],
                                 bh_[nt][0], bh_[nt][1]);
                        MMA_BF16(accu[mt][nt], ah[mt][0], ah[mt][1], ah[mt][2], ah[mt][3],
                                 bh_[nt][0], bh_[nt][1]);
                    }
            }
        }
        __syncthreads();
    }

#pragma unroll
    for (int mt = 0; mt < 2; ++mt) {
#pragma unroll
        for (int nt = 0; nt < 4; ++nt) {
            int r0 = m0 + wm + mt * 16 + gid;
            int c  = n0 + wn + nt * 8 + tig * 2;
#pragma unroll
            for (int half = 0; half < 2; ++half) {
                int rr = r0 + half * 8;
                float gv0 = accg[mt][nt][2 * half],     uv0 = accu[mt][nt][2 * half];
                float gv1 = accg[mt][nt][2 * half + 1], uv1 = accu[mt][nt][2 * half + 1];
                float a0 = gv0 * sigmoidf_(gv0) * uv0;
                float a1 = gv1 * sigmoidf_(gv1) * uv1;
                bf16 h0, l0, h1, l1;
                split_bf16(a0, h0, l0);
                split_bf16(a1, h1, l1);
                size_t o = (size_t)rr * Nfull + c;
                *reinterpret_cast<bf162*>(out_hi + o) = __halves2bfloat162(h0, h1);
                *reinterpret_cast<bf162*>(out_lo + o) = __halves2bfloat162(l0, l1);
            }
        }
    }
}

// ---------------------------------------------------------------------------
// RMSNorm with optional split-K partial reduction (H=512, block=128).
// npart (0/2/4): x = xin + p0 + p1 (+ p2 + p3), written back to xout.
// split!=0: write bf16 hi/lo; else fp32 out (final norm -> d_out).
// ---------------------------------------------------------------------------
__global__ __launch_bounds__(128) void rmsnorm_kernel(
    const float* __restrict__ xin, const float* __restrict__ p0,
    const float* __restrict__ p1, const float* __restrict__ p2,
    const float* __restrict__ p3, const float* __restrict__ w,
    float* __restrict__ xout, float* __restrict__ out,
    bf16* __restrict__ out_hi, bf16* __restrict__ out_lo,
    int npart, int split)
{
    const int row = blockIdx.x, tid = threadIdx.x;
    float4 v = reinterpret_cast<const float4*>(xin + (size_t)row * HDIM)[tid];
    if (npart > 0) {
        float4 a = reinterpret_cast<const float4*>(p0 + (size_t)row * HDIM)[tid];
        float4 b = reinterpret_cast<const float4*>(p1 + (size_t)row * HDIM)[tid];
        v.x += a.x + b.x; v.y += a.y + b.y;
        v.z += a.z + b.z; v.w += a.w + b.w;
        if (npart > 2) {
            float4 c = reinterpret_cast<const float4*>(p2 + (size_t)row * HDIM)[tid];
            float4 e = reinterpret_cast<const float4*>(p3 + (size_t)row * HDIM)[tid];
            v.x += c.x + e.x; v.y += c.y + e.y;
            v.z += c.z + e.z; v.w += c.w + e.w;
        }
        reinterpret_cast<float4*>(xout + (size_t)row * HDIM)[tid] = v;
    }
    float ss = v.x * v.x + v.y * v.y + v.z * v.z + v.w * v.w;
#pragma unroll
    for (int o = 16; o; o >>= 1) ss += __shfl_xor_sync(0xffffffffu, ss, o);
    __shared__ float sred[4];
    if ((tid & 31) == 0) sred[tid >> 5] = ss;
    __syncthreads();
    float tot = sred[0] + sred[1] + sred[2] + sred[3];
    float inv = rsqrtf(tot * (1.0f / (float)HDIM) + EPSV);
    float4 wv = reinterpret_cast<const float4*>(w)[tid];
    float4 o4 = make_float4(v.x * inv * wv.x, v.y * inv * wv.y,
                            v.z * inv * wv.z, v.w * inv * wv.w);
    if (split) {
        bf16 hx, lx, hy, ly, hz, lz, hw, lw;
        split_bf16(o4.x, hx, lx); split_bf16(o4.y, hy, ly);
        split_bf16(o4.z, hz, lz); split_bf16(o4.w, hw, lw);
        bf162* oh = reinterpret_cast<bf162*>(out_hi + (size_t)row * HDIM);
        bf162* ol = reinterpret_cast<bf162*>(out_lo + (size_t)row * HDIM);
        oh[tid * 2]     = __halves2bfloat162(hx, hy);
        oh[tid * 2 + 1] = __halves2bfloat162(hz, hw);
        ol[tid * 2]     = __halves2bfloat162(lx, ly);
        ol[tid * 2 + 1] = __halves2bfloat162(lz, lw);
    } else {
        reinterpret_cast<float4*>(out + (size_t)row * HDIM)[tid] = o4;
    }
}

// ---------------------------------------------------------------------------
// mLSTM step (zero state) + per-head RMSNorm + output gate.
// ---------------------------------------------------------------------------
__global__ __launch_bounds__(256) void mlstm_kernel(
    const float* __restrict__ q, const float* __restrict__ k,
    const float* __restrict__ v, const float* __restrict__ ogp,
    const float* __restrict__ ifp,
    const float* __restrict__ bi, const float* __restrict__ bf,
    const float* __restrict__ mhw,
    bf16* __restrict__ hv_hi, bf16* __restrict__ hv_lo)
{
    const int t = blockIdx.x;
    const int h = threadIdx.x >> 5;
    const int lane = threadIdx.x & 31;

    float ip = softcapf(ifp[(size_t)t * 64 + h]      + bi[h]);
    float fp = softcapf(ifp[(size_t)t * 64 + 8 + h]  + bf[h]);
    float flog = logsigf(fp);
    float m = fmaxf(flog, ip);
    float iact = expf(ip - m);

    float qd = q[(size_t)t * QKDIM + h * DHQK + lane];
    float kd = k[(size_t)t * QKDIM + h * DHQK + lane];
    float s = qd * kd;
#pragma unroll
    for (int o = 16; o; o >>= 1) s += __shfl_xor_sync(0xffffffffu, s, o);
    s *= 0.17677669529663687f;  // 32^-0.5

    float qn = iact * s;
    float denom = fmaxf(fabsf(qn), expf(-m)) + EPSV;
    float c = iact * s / denom;

    const int base = t * VDIM + h * DHV;
    float v0 = v[base + lane], v1 = v[base + 32 + lane];
    float h0 = c * v0, h1 = c * v1;

    float ms = h0 * h0 + h1 * h1;
#pragma unroll
    for (int o = 16; o; o >>= 1) ms += __shfl_xor_sync(0xffffffffu, ms, o);
    float inv = rsqrtf(ms * (1.0f / (float)DHV) + EPSV);

    float w0 = mhw[h * DHV + lane],      w1 = mhw[h * DHV + 32 + lane];
    float g0 = sigmoidf_(ogp[base + lane]);
    float g1 = sigmoidf_(ogp[base + 32 + lane]);
    float r0 = h0 * inv * w0 * g0;
    float r1 = h1 * inv * w1 * g1;
    bf16 rh, rl;
    split_bf16(r0, rh, rl);
    hv_hi[base + lane] = rh;           hv_lo[base + lane] = rl;
    split_bf16(r1, rh, rl);
    hv_hi[base + 32 + lane] = rh;      hv_lo[base + 32 + lane] = rl;
}

// ---------------------------------------------------------------------------
// Host launcher
// ---------------------------------------------------------------------------
static inline void* sym_addr_v(const void* sym) {
    void* p = nullptr;
    cudaGetSymbolAddress(&p, sym);
    return p;
}
#define SYMF(s)  ((float*)sym_addr_v(s))
#define SYMB(s)  ((bf16*)sym_addr_v(s))

static inline void gemm_multi(const bf16* Ahi, const bf16* Alo,
                              int M, int K, const GemmDesc& d) {
    int nb = d.seg[d.nseg - 1].nstart + d.seg[d.nseg - 1].N / BN;
    dim3 grid(nb, M / BM);
    gemm_bf16x3_kernel<<<grid, 128>>>(Ahi, Alo, M, K, d);
}

extern "C" void kernel_launch(void* const* d_in, const int* in_sizes, int n_in,
                              void* d_out, int out_size)
{
    (void)in_sizes; (void)n_in; (void)out_size;
    const float* u       = (const float*)d_in[0];
    const float* norm1_w = (const float*)d_in[1];
    const float* Wq      = (const float*)d_in[2];
    const float* Wk      = (const float*)d_in[3];
    const float* Wv      = (const float*)d_in[4];
    const float* Wi      = (const float*)d_in[5];
    const float* bi      = (const float*)d_in[6];
    const float* Wf      = (const float*)d_in[7];
    const float* bf_     = (const float*)d_in[8];
    const float* mh_w    = (const float*)d_in[9];
    const float* Wog     = (const float*)d_in[10];
    const float* Wout    = (const float*)d_in[11];
    const float* norm2_w = (const float*)d_in[12];
    const float* W_up    = (const float*)d_in[13];
    const float* W_gate  = (const float*)d_in[14];
    const float* W_down  = (const float*)d_in[15];
    const float* final_w = (const float*)d_in[16];
    float* out = (float*)d_out;

    cudaFuncSetAttribute(gemm_paired_kernel,
                         cudaFuncAttributeMaxDynamicSharedMemorySize, 2 * PST);

    float* x   = SYMF(g_x);
    float* qb  = SYMF(g_q);
    float* kb  = SYMF(g_k);
    float* vb  = SYMF(g_v);
    float* ogb = SYMF(g_og);
    float* ifb = SYMF(g_if);
    float* p0  = SYMF(g_p0);
    float* p1  = SYMF(g_p1);
    float* p2  = SYMF(g_p2);
    float* p3  = SYMF(g_p3);
    bf16* xnh  = SYMB(g_xn_h),  *xnl  = SYMB(g_xn_l);
    bf16* hvh  = SYMB(g_hv_h),  *hvl  = SYMB(g_hv_l);
    bf16* acth = SYMB(g_act_h), *actl = SYMB(g_act_l);

    bf16* wqh = SYMB(w_q_h),  *wql = SYMB(w_q_l);
    bf16* wkh = SYMB(w_k_h),  *wkl = SYMB(w_k_l);
    bf16* wvh = SYMB(w_v_h),  *wvl = SYMB(w_v_l);
    bf16* wogh= SYMB(w_og_h), *wogl= SYMB(w_og_l);
    bf16* woh = SYMB(w_o_h),  *wol = SYMB(w_o_l);
    bf16* wgh = SYMB(w_g_h),  *wgl = SYMB(w_g_l);
    bf16* wuh = SYMB(w_u_h),  *wul = SYMB(w_u_l);
    bf16* wdh = SYMB(w_d_h),  *wdl = SYMB(w_d_l);
    bf16* wifh= SYMB(w_if_h), *wifl= SYMB(w_if_l);

    copy_kernel<<<(NTOK * HDIM / 4 + 255) / 256, 256>>>(u, x, NTOK * HDIM / 4);

    {
        SplitDesc sd;
        sd.nseg = 3;
        sd.seg[0] = { W_gate, wgh, wgl, HDIM, FDIM, 0    };
        sd.seg[1] = { W_up,   wuh, wul, HDIM, FDIM, 704  };
        sd.seg[2] = { W_down, wdh, wdl, FDIM, HDIM, 1408 };
        dim3 grid(2112, 1, LAYERS);
        split_transpose_multi_kernel<<<grid, dim3(32, 8)>>>(sd);
    }
    {
        SplitDesc sd;
        sd.nseg = 5;
        sd.seg[0] = { Wq,   wqh,  wql,  HDIM, QKDIM, 0   };
        sd.seg[1] = { Wk,   wkh,  wkl,  HDIM, QKDIM, 128 };
        sd.seg[2] = { Wv,   wvh,  wvl,  HDIM, VDIM,  256 };
        sd.seg[3] = { Wog,  wogh, wogl, HDIM, VDIM,  512 };
        sd.seg[4] = { Wout, woh,  wol,  VDIM, HDIM,  768 };
        dim3 grid(1024, 1, LAYERS);
        split_transpose_multi_kernel<<<grid, dim3(32, 8)>>>(sd);
    }
    pack_wif_kernel<<<LAYERS * 64, 128>>>(Wi, Wf, wifh, wifl);

    int pending = 0;   // partials pending for next rmsnorm (0 or 4)

    for (int l = 0; l < LAYERS; ++l) {
        const size_t oqk = (size_t)l * QKDIM * HDIM;
        const size_t ov  = (size_t)l * VDIM * HDIM;
        const size_t of  = (size_t)l * FDIM * HDIM;
        const size_t oif = (size_t)l * 64 * HDIM;

        // --- mLSTM block ---
        rmsnorm_kernel<<<NTOK, 128>>>(x, p0, p1, p2, p3, norm1_w + l * HDIM,
                                      x, nullptr, xnh, xnl, pending, 1);

        GemmDesc d1;            // q | k | v | og | if
        d1.nseg = 5;
        d1.seg[0] = { wqh + oqk,  wql + oqk,  qb,  nullptr, QKDIM, 0,  0, HDIM };
        d1.seg[1] = { wkh + oqk,  wkl + oqk,  kb,  nullptr, QKDIM, 4,  0, HDIM };
        d1.seg[2] = { wvh + ov,   wvl + ov,   vb,  nullptr, VDIM,  8,  0, HDIM };
        d1.seg[3] = { wogh + ov,  wogl + ov,  ogb, nullptr, VDIM,  16, 0, HDIM };
        d1.seg[4] = { wifh + oif, wifl + oif, ifb, nullptr, 64,    24, 0, HDIM };
        gemm_multi(xnh, xnl, NTOK, HDIM, d1);

        mlstm_kernel<<<NTOK, 256>>>(qb, kb, vb, ogb, ifb,
                                    bi + l * NHEAD, bf_ + l * NHEAD,
                                    mh_w + (size_t)l * NHEAD * DHV, hvh, hvl);

        GemmDesc d2;            // hv @ Wout -> p0..p3 (split-K=4)
        d2.nseg = 4;
        d2.seg[0] = { woh + ov, wol + ov, p0, nullptr, HDIM, 0,  0,   128 };
        d2.seg[1] = { woh + ov, wol + ov, p1, nullptr, HDIM, 8,  128, 128 };
        d2.seg[2] = { woh + ov, wol + ov, p2, nullptr, HDIM, 16, 256, 128 };
        d2.seg[3] = { woh + ov, wol + ov, p3, nullptr, HDIM, 24, 384, 128 };
        gemm_multi(hvh, hvl, NTOK, VDIM, d2);

        // --- FFN block ---
        rmsnorm_kernel<<<NTOK, 128>>>(x, p0, p1, p2, p3, norm2_w + l * HDIM,
                                      x, nullptr, xnh, xnl, 4, 1);

        {
            dim3 grid(FDIM / BN, NTOK / BM);
            gemm_paired_kernel<<<grid, 128, 2 * PST>>>(
                xnh, xnl, wgh + of, wgl + of, wuh + of, wul + of,
                acth, actl, NTOK, HDIM, FDIM);
        }

        GemmDesc d4;            // act @ W_down -> p0..p3 (split-K=4)
        const size_t od = (size_t)l * HDIM * FDIM;
        d4.nseg = 4;
        d4.seg[0] = { wdh + od, wdl + od, p0, nullptr, HDIM, 0,  0,    352 };
        d4.seg[1] = { wdh + od, wdl + od, p1, nullptr, HDIM, 8,  352,  352 };
        d4.seg[2] = { wdh + od, wdl + od, p2, nullptr, HDIM, 16, 704,  352 };
        d4.seg[3] = { wdh + od, wdl + od, p3, nullptr, HDIM, 24, 1056, 352 };
        gemm_multi(acth, actl, NTOK, FDIM, d4);
        pending = 4;
    }

    // final rmsnorm reduces layer-3 d4 partials, writes fp32 d_out
    rmsnorm_kernel<<<NTOK, 128>>>(x, p0, p1, p2, p3, final_w,
                                  x, out, nullptr, nullptr, 4, 0);
}